// round 10
// baseline (speedup 1.0000x reference)
#include <cuda_runtime.h>
#include <cuda_bf16.h>
#include <math.h>
#include <stdint.h>

#define VN    8192
#define NCOL  64
#define KA    72            // smem row stride in bf16 (144B, LDSM conflict-free)

// smem plane byte offsets within one buffer (M-tile 64, k-tile 64)
#define AHI_OFF 0
#define ALO_OFF 9216        // 64*72*2
#define BHI_OFF 18432
#define BLO_OFF 27648
#define BUFSZ   36864
#define STAGES  3
#define DSMEM_GEMM (STAGES*BUFSZ)   // 110592

// ---------------- device scratch ---------------------------------------------
__device__ __nv_bfloat16 g_adjh[(size_t)VN * VN];   // blended adj, bf16 hi
__device__ __nv_bfloat16 g_adjl[(size_t)VN * VN];   // bf16 lo residual
__device__ float g_rowsum[VN];
__device__ float g_part[2][(size_t)VN * NCOL];
__device__ float g_X[(size_t)VN * NCOL];            // hop output [v][col]
__device__ __nv_bfloat16 g_XTh[(size_t)NCOL * VN];  // B operand, split, [col][w]
__device__ __nv_bfloat16 g_XTl[(size_t)NCOL * VN];
__device__ float g_w4[4];
__device__ float g_s1[256 * 128];
__device__ float g_s2[256 * 128];
__device__ float g_mu[128];
__device__ float g_rstd[128];

// ---------------- helpers ------------------------------------------------------
__device__ __forceinline__ uint32_t smem_u32(const void* p) {
    uint32_t a;
    asm("{ .reg .u64 t; cvta.to.shared.u64 t, %1; cvt.u32.u64 %0, t; }" : "=r"(a) : "l"(p));
    return a;
}
__device__ __forceinline__ void bsplit(float x, float y, uint32_t& hi, uint32_t& lo) {
    __nv_bfloat162 h = __floats2bfloat162_rn(x, y);
    float hx = __bfloat162float(h.x), hy = __bfloat162float(h.y);
    __nv_bfloat162 l = __floats2bfloat162_rn(x - hx, y - hy);
    hi = *reinterpret_cast<uint32_t*>(&h);
    lo = *reinterpret_cast<uint32_t*>(&l);
}
__device__ __forceinline__ void mma_bf16(float* c,
    uint32_t a0, uint32_t a1, uint32_t a2, uint32_t a3, uint32_t b0, uint32_t b1) {
    asm volatile(
        "mma.sync.aligned.m16n8k16.row.col.f32.bf16.bf16.f32 "
        "{%0,%1,%2,%3}, {%4,%5,%6,%7}, {%8,%9}, {%0,%1,%2,%3};"
        : "+f"(c[0]), "+f"(c[1]), "+f"(c[2]), "+f"(c[3])
        : "r"(a0), "r"(a1), "r"(a2), "r"(a3), "r"(b0), "r"(b1));
}
__device__ __forceinline__ void ldsm4(uint32_t addr, uint32_t* r) {
    asm volatile("ldmatrix.sync.aligned.m8n8.x4.shared.b16 {%0,%1,%2,%3}, [%4];"
        : "=r"(r[0]), "=r"(r[1]), "=r"(r[2]), "=r"(r[3]) : "r"(addr));
}
__device__ __forceinline__ void cpa16(uint32_t dst, const void* src) {
    asm volatile("cp.async.cg.shared.global [%0], [%1], 16;" :: "r"(dst), "l"(src) : "memory");
}
#define CP_COMMIT() asm volatile("cp.async.commit_group;" ::: "memory")

// one 64x64x64 k-tile; warp = 16 rows x 32 cols.
// 3 split terms accumulate into INDEPENDENT register sets (no RAW chains).
__device__ __forceinline__ void mma_tile(uint32_t base,
        float a1c[4][4], float a2c[4][4], float a3c[4][4],
        uint32_t aoff, const uint32_t* boff) {
#pragma unroll
    for (int ks = 0; ks < 4; ++ks) {
        const uint32_t kb = ks * 32;
        uint32_t ah[4], al[4];
        ldsm4(base + AHI_OFF + aoff + kb, ah);
        ldsm4(base + ALO_OFF + aoff + kb, al);
#pragma unroll
        for (int g = 0; g < 2; ++g) {
            uint32_t bh[4], bl[4];
            ldsm4(base + BHI_OFF + boff[g] + kb, bh);
            ldsm4(base + BLO_OFF + boff[g] + kb, bl);
            mma_bf16(a1c[2*g],   ah[0],ah[1],ah[2],ah[3], bh[0],bh[1]);
            mma_bf16(a2c[2*g],   ah[0],ah[1],ah[2],ah[3], bl[0],bl[1]);
            mma_bf16(a3c[2*g],   al[0],al[1],al[2],al[3], bh[0],bh[1]);
            mma_bf16(a1c[2*g+1], ah[0],ah[1],ah[2],ah[3], bh[2],bh[3]);
            mma_bf16(a2c[2*g+1], ah[0],ah[1],ah[2],ah[3], bl[2],bl[3]);
            mma_bf16(a3c[2*g+1], al[0],al[1],al[2],al[3], bh[2],bh[3]);
        }
    }
}

// warp layout: rw = wid>>1 (M group of 16), cw = wid&1 (N group of 32)
__device__ __forceinline__ void frag_offsets(int lane, int wid, uint32_t& aoff, uint32_t* boff) {
    const int rr = lane & 7, sel = lane >> 3;
    const int rw = wid >> 1, cw = wid & 1;
    aoff = ((rw * 16 + (sel & 1) * 8 + rr) * KA + (sel >> 1) * 8) * 2;
#pragma unroll
    for (int g = 0; g < 2; ++g)
        boff[g] = ((cw * 32 + g * 16 + (sel >> 1) * 8 + rr) * KA + (sel & 1) * 8) * 2;
}

__device__ __forceinline__ void write_partials(float a1c[4][4], float a2c[4][4],
        float a3c[4][4], int s, int vbase, int wid, int lane) {
    const int rw = wid >> 1, cw = wid & 1;
    float* dst = g_part[s] + (size_t)(vbase + rw * 16) * NCOL + cw * 32;
    const int gr = lane >> 2, cq = (lane & 3) * 2;
#pragma unroll
    for (int nb = 0; nb < 4; ++nb) {
        const int col = nb * 8 + cq;
        float v0 = a1c[nb][0] + a2c[nb][0] + a3c[nb][0];
        float v1 = a1c[nb][1] + a2c[nb][1] + a3c[nb][1];
        float v2 = a1c[nb][2] + a2c[nb][2] + a3c[nb][2];
        float v3 = a1c[nb][3] + a2c[nb][3] + a3c[nb][3];
        *(float2*)(dst + (size_t)gr * NCOL + col)       = make_float2(v0, v1);
        *(float2*)(dst + (size_t)(gr + 8) * NCOL + col) = make_float2(v2, v3);
    }
}

// ---------------- alpha softmax ----------------------------------------------
__global__ void k_alpha(const float* __restrict__ af, const float* __restrict__ as) {
    float e0 = expf(af[0]), e1 = expf(af[1]);
    g_w4[0] = e0 / (e0 + e1); g_w4[1] = e1 / (e0 + e1);
    float f0 = expf(as[0]), f1 = expf(as[1]);
    g_w4[2] = f0 / (f0 + f1); g_w4[3] = f1 / (f0 + f1);
}

// ---------------- prep: data -> split transposed B ([col][w]) -----------------
__global__ __launch_bounds__(256) void k_prepB(const float* __restrict__ data) {
    int fidx = blockIdx.x * 256 + threadIdx.x;   // 131072 float4s
    int col = fidx >> 11;
    int w4  = (fidx & 2047) << 2;
    float4 v = *(const float4*)(data + (size_t)col * 16384 + w4);
    uint32_t h0, l0, h1, l1;
    bsplit(v.x, v.y, h0, l0);
    bsplit(v.z, v.w, h1, l1);
    *reinterpret_cast<uint2*>(g_XTh + (size_t)col * VN + w4) = make_uint2(h0, h1);
    *reinterpret_cast<uint2*>(g_XTl + (size_t)col * VN + w4) = make_uint2(l0, l1);
}

// ---------------- blend: 5-stream -> split bf16 planes + rowsum ---------------
__global__ __launch_bounds__(256) void k_blend(
    const float* __restrict__ adjf, const float* __restrict__ adjs,
    const float* __restrict__ adjm)
{
    const int wid = threadIdx.x >> 5, lane = threadIdx.x & 31;
    const int row = blockIdx.x * 8 + wid;
    const size_t base = (size_t)row * VN;
    const float w0 = g_w4[0], w1 = g_w4[1], w2 = g_w4[2], w3 = g_w4[3];
    const float* __restrict__ a0 = adjf + base;
    const float* __restrict__ a1 = adjf + (size_t)VN * VN + base;
    const float* __restrict__ b0 = adjs + base;
    const float* __restrict__ b1 = adjs + (size_t)VN * VN + base;
    const float* __restrict__ m0 = adjm + base;
    __nv_bfloat16* __restrict__ dh = g_adjh + base;
    __nv_bfloat16* __restrict__ dl = g_adjl + base;
    float rs = 0.f;
    for (int i = lane; i < 2048; i += 64) {
#pragma unroll
        for (int u = 0; u < 2; ++u) {
            const int o4 = (i + u * 32) * 4;
            float4 a = *(const float4*)(a0 + o4);
            float4 b = *(const float4*)(a1 + o4);
            float4 c = *(const float4*)(b0 + o4);
            float4 d = *(const float4*)(b1 + o4);
            float4 m = *(const float4*)(m0 + o4);
            float4 r;
            r.x = fmaf(w0, a.x, fmaf(w1, b.x, fmaf(w2, c.x, fmaf(w3, d.x, m.x))));
            r.y = fmaf(w0, a.y, fmaf(w1, b.y, fmaf(w2, c.y, fmaf(w3, d.y, m.y))));
            r.z = fmaf(w0, a.z, fmaf(w1, b.z, fmaf(w2, c.z, fmaf(w3, d.z, m.z))));
            r.w = fmaf(w0, a.w, fmaf(w1, b.w, fmaf(w2, c.w, fmaf(w3, d.w, m.w))));
            rs += (r.x + r.y) + (r.z + r.w);
            uint32_t h0, l0, h1, l1;
            bsplit(r.x, r.y, h0, l0);
            bsplit(r.z, r.w, h1, l1);
            *reinterpret_cast<uint2*>(dh + o4) = make_uint2(h0, h1);
            *reinterpret_cast<uint2*>(dl + o4) = make_uint2(l0, l1);
        }
    }
    rs += __shfl_xor_sync(0xffffffffu, rs, 16);
    rs += __shfl_xor_sync(0xffffffffu, rs, 8);
    rs += __shfl_xor_sync(0xffffffffu, rs, 4);
    rs += __shfl_xor_sync(0xffffffffu, rs, 2);
    rs += __shfl_xor_sync(0xffffffffu, rs, 1);
    if (lane == 0) g_rowsum[row] = rs;
}

// ---------------- hop GEMM: 3-stage cp.async pipeline, 2 CTAs/SM --------------
// grid (128, 2): 64-row M tiles x split-K halves. 64 k-tiles per CTA.
__global__ __launch_bounds__(256, 2) void k_gemm()
{
    extern __shared__ __align__(16) char smem[];
    const uint32_t base = smem_u32(smem);
    const int tid = threadIdx.x, lane = tid & 31, wid = tid >> 5;
    const int vbase = blockIdx.x * 64;
    const int kbase = blockIdx.y * 4096;

    uint32_t aoff, boff[2];
    frag_offsets(lane, wid, aoff, boff);

    float a1c[4][4], a2c[4][4], a3c[4][4];
#pragma unroll
    for (int i = 0; i < 4; ++i)
#pragma unroll
        for (int j = 0; j < 4; ++j) { a1c[i][j] = 0.f; a2c[i][j] = 0.f; a3c[i][j] = 0.f; }

    auto issue = [&](int t) {
        const uint32_t dst = base + (uint32_t)(t % STAGES) * BUFSZ;
        const int kg = kbase + t * 64;
#pragma unroll
        for (int j = 0; j < 2; ++j) {
            const int id = tid + 256 * j;
            const int row = id >> 3, ch = id & 7;
            const size_t go = (size_t)(vbase + row) * VN + kg + ch * 8;
            const uint32_t so = (uint32_t)(row * KA + ch * 8) * 2;
            cpa16(dst + AHI_OFF + so, g_adjh + go);
            cpa16(dst + ALO_OFF + so, g_adjl + go);
        }
#pragma unroll
        for (int j = 0; j < 2; ++j) {
            const int id = tid + 256 * j;
            const int n = id >> 3, ch = id & 7;
            const size_t go = (size_t)n * VN + kg + ch * 8;
            const uint32_t so = (uint32_t)(n * KA + ch * 8) * 2;
            cpa16(dst + BHI_OFF + so, g_XTh + go);
            cpa16(dst + BLO_OFF + so, g_XTl + go);
        }
        CP_COMMIT();
    };

    issue(0); issue(1); issue(2);
    for (int t = 0; t < 64; ++t) {
        if (t <= 61)      asm volatile("cp.async.wait_group 2;" ::: "memory");
        else if (t == 62) asm volatile("cp.async.wait_group 1;" ::: "memory");
        else              asm volatile("cp.async.wait_group 0;" ::: "memory");
        __syncthreads();
        mma_tile(base + (uint32_t)(t % STAGES) * BUFSZ, a1c, a2c, a3c, aoff, boff);
        __syncthreads();
        if (t + STAGES < 64) issue(t + STAGES);
    }

    write_partials(a1c, a2c, a3c, blockIdx.y, vbase, wid, lane);
}

// ---------------- combine: partials -> g_X and split transposed B -------------
__global__ __launch_bounds__(256) void k_combine() {
    __shared__ float sm[64][65];
    __shared__ float rs[64];
    const int tid = threadIdx.x;
    const int vbase = blockIdx.x * 64;
    if (tid < 64) rs[tid] = g_rowsum[vbase + tid];
    __syncthreads();
#pragma unroll
    for (int j = 0; j < 4; ++j) {
        const int f = tid + j * 256;
        const int r = f >> 4, c = (f & 15) << 2;
        const size_t o = (size_t)(vbase + r) * NCOL + c;
        float4 p = *(const float4*)(g_part[0] + o);
        float4 q = *(const float4*)(g_part[1] + o);
        const float inv = 1.f / rs[r];
        float4 v;
        v.x = (p.x + q.x) * inv; v.y = (p.y + q.y) * inv;
        v.z = (p.z + q.z) * inv; v.w = (p.w + q.w) * inv;
        *(float4*)(g_X + o) = v;
        sm[r][c] = v.x; sm[r][c + 1] = v.y; sm[r][c + 2] = v.z; sm[r][c + 3] = v.w;
    }
    __syncthreads();
    const int col = tid >> 2;
    const int v0 = (tid & 3) << 4;
#pragma unroll
    for (int j = 0; j < 4; ++j) {
        const int v = v0 + j * 4;
        float4 x;
        x.x = sm[v][col]; x.y = sm[v + 1][col]; x.z = sm[v + 2][col]; x.w = sm[v + 3][col];
        uint32_t h0, l0, h1, l1;
        bsplit(x.x, x.y, h0, l0);
        bsplit(x.z, x.w, h1, l1);
        *reinterpret_cast<uint2*>(g_XTh + (size_t)col * VN + vbase + v) = make_uint2(h0, h1);
        *reinterpret_cast<uint2*>(g_XTl + (size_t)col * VN + vbase + v) = make_uint2(l0, l1);
    }
}

// ---------------- BN stats ---------------------------------------------------
__global__ __launch_bounds__(128) void k_stats(const float* __restrict__ W,
                                               const float* __restrict__ bias) {
    __shared__ float xs[1024];
    const int tid = threadIdx.x;
    const float* __restrict__ Xsrc = g_X + (size_t)4096 * NCOL + (size_t)blockIdx.x * 1024;
#pragma unroll
    for (int j = 0; j < 2; ++j)
        *(float4*)&xs[tid * 8 + j * 4] = *(const float4*)(Xsrc + tid * 8 + j * 4);
    __syncthreads();
    float w[16];
#pragma unroll
    for (int c = 0; c < 16; ++c) w[c] = W[tid * 16 + c];
    const float bb = bias[tid];
    float s = 0.f, ss = 0.f;
    for (int q = 0; q < 64; ++q) {
        const float* xq = &xs[q * 16];
        float y = bb;
#pragma unroll
        for (int c = 0; c < 16; ++c) y = fmaf(w[c], xq[c], y);
        s += y;
        ss = fmaf(y, y, ss);
    }
    g_s1[blockIdx.x * 128 + tid] = s;
    g_s2[blockIdx.x * 128 + tid] = ss;
}

__global__ void k_stats2() {
    const int o = threadIdx.x;
    float s = 0.f, ss = 0.f;
    for (int b2 = 0; b2 < 256; ++b2) { s += g_s1[b2 * 128 + o]; ss += g_s2[b2 * 128 + o]; }
    const float inv = 1.f / 16384.f;
    float mu = s * inv;
    float var = ss * inv - mu * mu;
    g_mu[o] = mu;
    g_rstd[o] = rsqrtf(var + 1e-5f);
}

// ---------------- GLU + BN apply + running max -------------------------------
__global__ __launch_bounds__(128) void k_glu(const float* __restrict__ W,
    const float* __restrict__ bias, const float* __restrict__ gamma,
    const float* __restrict__ beta, float* __restrict__ out, int first)
{
    __shared__ float Wsm[2048], bsm[128], gsm[128], besm[128], musm[128], rsm[128];
    const int tid = threadIdx.x;
    const int n = blockIdx.x * 128 + tid;
    const int b = blockIdx.y;
#pragma unroll
    for (int j = 0; j < 16; ++j) Wsm[tid * 16 + j] = W[tid * 16 + j];
    bsm[tid] = bias[tid]; gsm[tid] = gamma[tid]; besm[tid] = beta[tid];
    musm[tid] = g_mu[tid]; rsm[tid] = g_rstd[tid];
    __syncthreads();

    float xr[16];
    const float* __restrict__ xp = g_X + (size_t)4096 * NCOL + (size_t)n * 64 + b * 16;
#pragma unroll
    for (int j = 0; j < 4; ++j) {
        float4 t = *(const float4*)(xp + j * 4);
        xr[j * 4] = t.x; xr[j * 4 + 1] = t.y; xr[j * 4 + 2] = t.z; xr[j * 4 + 3] = t.w;
    }
    float* op = out + (size_t)b * (64 * 4096) + n;
    for (int f = 0; f < 64; ++f) {
        const float* wl = &Wsm[f * 16];
        const float* wr = &Wsm[(f + 64) * 16];
        float yl = bsm[f], yr = bsm[f + 64];
#pragma unroll
        for (int c = 0; c < 16; ++c) {
            yl = fmaf(wl[c], xr[c], yl);
            yr = fmaf(wr[c], xr[c], yr);
        }
        yl = fmaf(gsm[f] * (yl - musm[f]), rsm[f], besm[f]);
        yr = fmaf(gsm[f + 64] * (yr - musm[f + 64]), rsm[f + 64], besm[f + 64]);
        float val = yl / (1.f + expf(-yr));
        float* po = op + (size_t)f * 4096;
        if (first) *po = val;
        else       *po = fmaxf(*po, val);
    }
}

// ---------------- launch -----------------------------------------------------
extern "C" void kernel_launch(void* const* d_in, const int* in_sizes, int n_in,
                              void* d_out, int out_size)
{
    (void)in_sizes; (void)n_in; (void)out_size;
    const float* adjf = (const float*)d_in[0];
    const float* adjs = (const float*)d_in[1];
    const float* adjm = (const float*)d_in[2];
    const float* data = (const float*)d_in[3];
    const float* alf  = (const float*)d_in[4];
    const float* als  = (const float*)d_in[5];
    const float* gw   = (const float*)d_in[6];
    const float* gb   = (const float*)d_in[7];
    const float* gg   = (const float*)d_in[8];
    const float* gbe  = (const float*)d_in[9];
    float* out = (float*)d_out;

    cudaFuncSetAttribute(k_gemm, cudaFuncAttributeMaxDynamicSharedMemorySize, DSMEM_GEMM);

    k_alpha<<<1, 1>>>(alf, als);
    k_prepB<<<512, 256>>>(data);
    k_blend<<<1024, 256>>>(adjf, adjs, adjm);

    for (int h = 0; h < 3; ++h) {
        k_gemm<<<dim3(128, 2), 256, DSMEM_GEMM>>>();
        k_combine<<<128, 256>>>();
        k_stats<<<256, 128>>>(gw + h * 2048, gb + h * 128);
        k_stats2<<<1, 128>>>();
        k_glu<<<dim3(32, 4), 128>>>(gw + h * 2048, gb + h * 128,
                                    gg + h * 128, gbe + h * 128, out, h == 0 ? 1 : 0);
    }
}

// round 11
// speedup vs baseline: 1.0402x; 1.0402x over previous
#include <cuda_runtime.h>
#include <cuda_bf16.h>
#include <math.h>
#include <stdint.h>

#define VN    8192
#define NCOL  64
#define KA    72            // smem row stride in bf16 (144B, LDSM conflict-free)

// smem plane byte offsets within one buffer (M-tile 64, k-tile 64)
#define AHI_OFF 0
#define ALO_OFF 9216        // 64*72*2
#define BHI_OFF 18432
#define BLO_OFF 27648
#define BUFSZ   36864
#define STAGES  3
#define DSMEM_GEMM (STAGES*BUFSZ)   // 110592

// ---------------- device scratch ---------------------------------------------
__device__ __nv_bfloat16 g_adjh[(size_t)VN * VN];   // blended adj, bf16 hi
__device__ __nv_bfloat16 g_adjl[(size_t)VN * VN];   // bf16 lo residual
__device__ float g_rowsum[VN];
__device__ float g_part[2][(size_t)VN * NCOL];
__device__ float g_X[(size_t)VN * NCOL];            // hop output [v][col]
__device__ __nv_bfloat16 g_XTh[(size_t)NCOL * VN];  // B operand, split, [col][w]
__device__ __nv_bfloat16 g_XTl[(size_t)NCOL * VN];
__device__ float g_s1[64 * 128];                    // BN partials [sblk][o]
__device__ float g_s2[64 * 128];

// ---------------- helpers ------------------------------------------------------
__device__ __forceinline__ uint32_t smem_u32(const void* p) {
    uint32_t a;
    asm("{ .reg .u64 t; cvta.to.shared.u64 t, %1; cvt.u32.u64 %0, t; }" : "=r"(a) : "l"(p));
    return a;
}
__device__ __forceinline__ void bsplit(float x, float y, uint32_t& hi, uint32_t& lo) {
    __nv_bfloat162 h = __floats2bfloat162_rn(x, y);
    float hx = __bfloat162float(h.x), hy = __bfloat162float(h.y);
    __nv_bfloat162 l = __floats2bfloat162_rn(x - hx, y - hy);
    hi = *reinterpret_cast<uint32_t*>(&h);
    lo = *reinterpret_cast<uint32_t*>(&l);
}
__device__ __forceinline__ void mma_bf16(float* c,
    uint32_t a0, uint32_t a1, uint32_t a2, uint32_t a3, uint32_t b0, uint32_t b1) {
    asm volatile(
        "mma.sync.aligned.m16n8k16.row.col.f32.bf16.bf16.f32 "
        "{%0,%1,%2,%3}, {%4,%5,%6,%7}, {%8,%9}, {%0,%1,%2,%3};"
        : "+f"(c[0]), "+f"(c[1]), "+f"(c[2]), "+f"(c[3])
        : "r"(a0), "r"(a1), "r"(a2), "r"(a3), "r"(b0), "r"(b1));
}
__device__ __forceinline__ void ldsm4(uint32_t addr, uint32_t* r) {
    asm volatile("ldmatrix.sync.aligned.m8n8.x4.shared.b16 {%0,%1,%2,%3}, [%4];"
        : "=r"(r[0]), "=r"(r[1]), "=r"(r[2]), "=r"(r[3]) : "r"(addr));
}
__device__ __forceinline__ void cpa16(uint32_t dst, const void* src) {
    asm volatile("cp.async.cg.shared.global [%0], [%1], 16;" :: "r"(dst), "l"(src) : "memory");
}
#define CP_COMMIT() asm volatile("cp.async.commit_group;" ::: "memory")

// one 64x64x64 k-tile; warp = 16 rows x 32 cols, 3-term bf16 split (chained acc)
__device__ __forceinline__ void mma_tile(uint32_t base, float acc[4][4],
                                         uint32_t aoff, const uint32_t* boff) {
#pragma unroll
    for (int ks = 0; ks < 4; ++ks) {
        const uint32_t kb = ks * 32;
        uint32_t ah[4], al[4];
        ldsm4(base + AHI_OFF + aoff + kb, ah);
        ldsm4(base + ALO_OFF + aoff + kb, al);
#pragma unroll
        for (int g = 0; g < 2; ++g) {
            uint32_t bh[4], bl[4];
            ldsm4(base + BHI_OFF + boff[g] + kb, bh);
            ldsm4(base + BLO_OFF + boff[g] + kb, bl);
            mma_bf16(acc[2*g],   ah[0],ah[1],ah[2],ah[3], bh[0],bh[1]);
            mma_bf16(acc[2*g],   ah[0],ah[1],ah[2],ah[3], bl[0],bl[1]);
            mma_bf16(acc[2*g],   al[0],al[1],al[2],al[3], bh[0],bh[1]);
            mma_bf16(acc[2*g+1], ah[0],ah[1],ah[2],ah[3], bh[2],bh[3]);
            mma_bf16(acc[2*g+1], ah[0],ah[1],ah[2],ah[3], bl[2],bl[3]);
            mma_bf16(acc[2*g+1], al[0],al[1],al[2],al[3], bh[2],bh[3]);
        }
    }
}

// warp layout: rw = wid>>1 (M group of 16), cw = wid&1 (N group of 32)
__device__ __forceinline__ void frag_offsets(int lane, int wid, uint32_t& aoff, uint32_t* boff) {
    const int rr = lane & 7, sel = lane >> 3;
    const int rw = wid >> 1, cw = wid & 1;
    aoff = ((rw * 16 + (sel & 1) * 8 + rr) * KA + (sel >> 1) * 8) * 2;
#pragma unroll
    for (int g = 0; g < 2; ++g)
        boff[g] = ((cw * 32 + g * 16 + (sel >> 1) * 8 + rr) * KA + (sel & 1) * 8) * 2;
}

__device__ __forceinline__ void write_partials(float acc[4][4], int s, int vbase,
                                               int wid, int lane) {
    const int rw = wid >> 1, cw = wid & 1;
    float* dst = g_part[s] + (size_t)(vbase + rw * 16) * NCOL + cw * 32;
    const int gr = lane >> 2, cq = (lane & 3) * 2;
#pragma unroll
    for (int nb = 0; nb < 4; ++nb) {
        const int col = nb * 8 + cq;
        *(float2*)(dst + (size_t)gr * NCOL + col)       = make_float2(acc[nb][0], acc[nb][1]);
        *(float2*)(dst + (size_t)(gr + 8) * NCOL + col) = make_float2(acc[nb][2], acc[nb][3]);
    }
}

// ---------------- prep: data -> split transposed B ([col][w]) -----------------
__global__ __launch_bounds__(256) void k_prepB(const float* __restrict__ data) {
    int fidx = blockIdx.x * 256 + threadIdx.x;   // 131072 float4s
    int col = fidx >> 11;
    int w4  = (fidx & 2047) << 2;
    float4 v = *(const float4*)(data + (size_t)col * 16384 + w4);
    uint32_t h0, l0, h1, l1;
    bsplit(v.x, v.y, h0, l0);
    bsplit(v.z, v.w, h1, l1);
    *reinterpret_cast<uint2*>(g_XTh + (size_t)col * VN + w4) = make_uint2(h0, h1);
    *reinterpret_cast<uint2*>(g_XTl + (size_t)col * VN + w4) = make_uint2(l0, l1);
}

// ---------------- blend: 5-stream -> split bf16 planes + rowsum ---------------
__global__ __launch_bounds__(256) void k_blend(
    const float* __restrict__ adjf, const float* __restrict__ adjs,
    const float* __restrict__ adjm,
    const float* __restrict__ alf, const float* __restrict__ als)
{
    // alpha softmax inline (uniform per thread, deterministic)
    const float e0 = expf(alf[0]), e1 = expf(alf[1]);
    const float f0 = expf(als[0]), f1 = expf(als[1]);
    const float w0 = e0 / (e0 + e1), w1 = e1 / (e0 + e1);
    const float w2 = f0 / (f0 + f1), w3 = f1 / (f0 + f1);

    const int wid = threadIdx.x >> 5, lane = threadIdx.x & 31;
    const int row = blockIdx.x * 8 + wid;
    const size_t base = (size_t)row * VN;
    const float* __restrict__ a0 = adjf + base;
    const float* __restrict__ a1 = adjf + (size_t)VN * VN + base;
    const float* __restrict__ b0 = adjs + base;
    const float* __restrict__ b1 = adjs + (size_t)VN * VN + base;
    const float* __restrict__ m0 = adjm + base;
    __nv_bfloat16* __restrict__ dh = g_adjh + base;
    __nv_bfloat16* __restrict__ dl = g_adjl + base;
    float rs = 0.f;
    for (int i = lane; i < 2048; i += 64) {
#pragma unroll
        for (int u = 0; u < 2; ++u) {
            const int o4 = (i + u * 32) * 4;
            float4 a = *(const float4*)(a0 + o4);
            float4 b = *(const float4*)(a1 + o4);
            float4 c = *(const float4*)(b0 + o4);
            float4 d = *(const float4*)(b1 + o4);
            float4 m = *(const float4*)(m0 + o4);
            float4 r;
            r.x = fmaf(w0, a.x, fmaf(w1, b.x, fmaf(w2, c.x, fmaf(w3, d.x, m.x))));
            r.y = fmaf(w0, a.y, fmaf(w1, b.y, fmaf(w2, c.y, fmaf(w3, d.y, m.y))));
            r.z = fmaf(w0, a.z, fmaf(w1, b.z, fmaf(w2, c.z, fmaf(w3, d.z, m.z))));
            r.w = fmaf(w0, a.w, fmaf(w1, b.w, fmaf(w2, c.w, fmaf(w3, d.w, m.w))));
            rs += (r.x + r.y) + (r.z + r.w);
            uint32_t h0, l0, h1, l1;
            bsplit(r.x, r.y, h0, l0);
            bsplit(r.z, r.w, h1, l1);
            *reinterpret_cast<uint2*>(dh + o4) = make_uint2(h0, h1);
            *reinterpret_cast<uint2*>(dl + o4) = make_uint2(l0, l1);
        }
    }
    rs += __shfl_xor_sync(0xffffffffu, rs, 16);
    rs += __shfl_xor_sync(0xffffffffu, rs, 8);
    rs += __shfl_xor_sync(0xffffffffu, rs, 4);
    rs += __shfl_xor_sync(0xffffffffu, rs, 2);
    rs += __shfl_xor_sync(0xffffffffu, rs, 1);
    if (lane == 0) g_rowsum[row] = rs;
}

// ---------------- hop GEMM: 3-stage cp.async, ONE barrier per tile ------------
// grid (128, 2): 64-row M tiles x split-K halves. 64 k-tiles per CTA.
__global__ __launch_bounds__(256, 2) void k_gemm()
{
    extern __shared__ __align__(16) char smem[];
    const uint32_t base = smem_u32(smem);
    const int tid = threadIdx.x, lane = tid & 31, wid = tid >> 5;
    const int vbase = blockIdx.x * 64;
    const int kbase = blockIdx.y * 4096;

    uint32_t aoff, boff[2];
    frag_offsets(lane, wid, aoff, boff);

    float acc[4][4];
#pragma unroll
    for (int i = 0; i < 4; ++i)
#pragma unroll
        for (int j = 0; j < 4; ++j) acc[i][j] = 0.f;

    auto issue = [&](int t) {
        const uint32_t dst = base + (uint32_t)(t % STAGES) * BUFSZ;
        const int kg = kbase + t * 64;
#pragma unroll
        for (int j = 0; j < 2; ++j) {
            const int id = tid + 256 * j;
            const int row = id >> 3, ch = id & 7;
            const size_t go = (size_t)(vbase + row) * VN + kg + ch * 8;
            const uint32_t so = (uint32_t)(row * KA + ch * 8) * 2;
            cpa16(dst + AHI_OFF + so, g_adjh + go);
            cpa16(dst + ALO_OFF + so, g_adjl + go);
        }
#pragma unroll
        for (int j = 0; j < 2; ++j) {
            const int id = tid + 256 * j;
            const int n = id >> 3, ch = id & 7;
            const size_t go = (size_t)n * VN + kg + ch * 8;
            const uint32_t so = (uint32_t)(n * KA + ch * 8) * 2;
            cpa16(dst + BHI_OFF + so, g_XTh + go);
            cpa16(dst + BLO_OFF + so, g_XTl + go);
        }
        CP_COMMIT();
    };

    issue(0); issue(1);
    for (int t = 0; t < 64; ++t) {
        if (t < 63) asm volatile("cp.async.wait_group 1;" ::: "memory");
        else        asm volatile("cp.async.wait_group 0;" ::: "memory");
        __syncthreads();                 // tile t fully visible to all warps
        mma_tile(base + (uint32_t)(t % STAGES) * BUFSZ, acc, aoff, boff);
        // safe: slot (t+2)%3 == (t-1)%3; every warp finished mma(t-1) before
        // this iteration's barrier.
        if (t + 2 < 64) issue(t + 2);
    }

    write_partials(acc, blockIdx.y, vbase, wid, lane);
}

// ---------------- combine + fused BN stats -------------------------------------
// normalizes partials -> g_X; blocks with vbase>=4096 also emit per-channel
// BN partial sums from the staged tile; transpose-split B skipped on last hop.
__global__ __launch_bounds__(256) void k_combine(const float* __restrict__ W,
                                                 const float* __restrict__ bias,
                                                 int lastHop) {
    __shared__ float sm[64][65];
    __shared__ float rs[64];
    const int tid = threadIdx.x;
    const int vbase = blockIdx.x * 64;
    if (tid < 64) rs[tid] = g_rowsum[vbase + tid];
    __syncthreads();
#pragma unroll
    for (int j = 0; j < 4; ++j) {
        const int f = tid + j * 256;
        const int r = f >> 4, c = (f & 15) << 2;
        const size_t o = (size_t)(vbase + r) * NCOL + c;
        float4 p = *(const float4*)(g_part[0] + o);
        float4 q = *(const float4*)(g_part[1] + o);
        const float inv = 1.f / rs[r];
        float4 v;
        v.x = (p.x + q.x) * inv; v.y = (p.y + q.y) * inv;
        v.z = (p.z + q.z) * inv; v.w = (p.w + q.w) * inv;
        *(float4*)(g_X + o) = v;
        sm[r][c] = v.x; sm[r][c + 1] = v.y; sm[r][c + 2] = v.z; sm[r][c + 3] = v.w;
    }
    __syncthreads();
    if (!lastHop) {
        const int col = tid >> 2;
        const int v0 = (tid & 3) << 4;
#pragma unroll
        for (int j = 0; j < 4; ++j) {
            const int v = v0 + j * 4;
            float4 x;
            x.x = sm[v][col]; x.y = sm[v + 1][col]; x.z = sm[v + 2][col]; x.w = sm[v + 3][col];
            uint32_t h0, l0, h1, l1;
            bsplit(x.x, x.y, h0, l0);
            bsplit(x.z, x.w, h1, l1);
            *reinterpret_cast<uint2*>(g_XTh + (size_t)col * VN + vbase + v) = make_uint2(h0, h1);
            *reinterpret_cast<uint2*>(g_XTl + (size_t)col * VN + vbase + v) = make_uint2(l0, l1);
        }
    }
    // fused BN stats for the GLU segment (rows 4096..8191)
    if (vbase >= 4096 && tid < 128) {
        const int o = tid;
        float w[16];
#pragma unroll
        for (int c = 0; c < 16; ++c) w[c] = W[o * 16 + c];
        const float bb = bias[o];
        float s = 0.f, ss = 0.f;
        for (int r = 0; r < 64; ++r) {
#pragma unroll
            for (int b = 0; b < 4; ++b) {
                float y = bb;
#pragma unroll
                for (int c = 0; c < 16; ++c) y = fmaf(w[c], sm[r][b * 16 + c], y);
                s += y;
                ss = fmaf(y, y, ss);
            }
        }
        const int sblk = blockIdx.x - 64;
        g_s1[sblk * 128 + o] = s;
        g_s2[sblk * 128 + o] = ss;
    }
}

// ---------------- GLU + BN apply (inline stats2) + running max ----------------
__global__ __launch_bounds__(128) void k_glu(const float* __restrict__ W,
    const float* __restrict__ bias, const float* __restrict__ gamma,
    const float* __restrict__ beta, float* __restrict__ out, int first)
{
    __shared__ float Wsm[2048], bsm[128], gsm[128], besm[128], musm[128], rsm[128];
    const int tid = threadIdx.x;
    const int n = blockIdx.x * 128 + tid;
    const int b = blockIdx.y;
#pragma unroll
    for (int j = 0; j < 16; ++j) Wsm[tid * 16 + j] = W[tid * 16 + j];
    bsm[tid] = bias[tid]; gsm[tid] = gamma[tid]; besm[tid] = beta[tid];
    {   // inline stats2: reduce 64 partial blocks (L2-resident)
        float s = 0.f, ss = 0.f;
        for (int k = 0; k < 64; ++k) { s += g_s1[k * 128 + tid]; ss += g_s2[k * 128 + tid]; }
        const float inv = 1.f / 16384.f;
        const float mu = s * inv;
        const float var = ss * inv - mu * mu;
        musm[tid] = mu;
        rsm[tid] = rsqrtf(var + 1e-5f);
    }
    __syncthreads();

    float xr[16];
    const float* __restrict__ xp = g_X + (size_t)4096 * NCOL + (size_t)n * 64 + b * 16;
#pragma unroll
    for (int j = 0; j < 4; ++j) {
        float4 t = *(const float4*)(xp + j * 4);
        xr[j * 4] = t.x; xr[j * 4 + 1] = t.y; xr[j * 4 + 2] = t.z; xr[j * 4 + 3] = t.w;
    }
    float* op = out + (size_t)b * (64 * 4096) + n;
    for (int f = 0; f < 64; ++f) {
        const float* wl = &Wsm[f * 16];
        const float* wr = &Wsm[(f + 64) * 16];
        float yl = bsm[f], yr = bsm[f + 64];
#pragma unroll
        for (int c = 0; c < 16; ++c) {
            yl = fmaf(wl[c], xr[c], yl);
            yr = fmaf(wr[c], xr[c], yr);
        }
        yl = fmaf(gsm[f] * (yl - musm[f]), rsm[f], besm[f]);
        yr = fmaf(gsm[f + 64] * (yr - musm[f + 64]), rsm[f + 64], besm[f + 64]);
        float val = yl / (1.f + expf(-yr));
        float* po = op + (size_t)f * 4096;
        if (first) *po = val;
        else       *po = fmaxf(*po, val);
    }
}

// ---------------- launch -----------------------------------------------------
extern "C" void kernel_launch(void* const* d_in, const int* in_sizes, int n_in,
                              void* d_out, int out_size)
{
    (void)in_sizes; (void)n_in; (void)out_size;
    const float* adjf = (const float*)d_in[0];
    const float* adjs = (const float*)d_in[1];
    const float* adjm = (const float*)d_in[2];
    const float* data = (const float*)d_in[3];
    const float* alf  = (const float*)d_in[4];
    const float* als  = (const float*)d_in[5];
    const float* gw   = (const float*)d_in[6];
    const float* gb   = (const float*)d_in[7];
    const float* gg   = (const float*)d_in[8];
    const float* gbe  = (const float*)d_in[9];
    float* out = (float*)d_out;

    cudaFuncSetAttribute(k_gemm, cudaFuncAttributeMaxDynamicSharedMemorySize, DSMEM_GEMM);

    k_prepB<<<512, 256>>>(data);
    k_blend<<<1024, 256>>>(adjf, adjs, adjm, alf, als);

    for (int h = 0; h < 3; ++h) {
        k_gemm<<<dim3(128, 2), 256, DSMEM_GEMM>>>();
        k_combine<<<128, 256>>>(gw + h * 2048, gb + h * 128, h == 2 ? 1 : 0);
        k_glu<<<dim3(32, 4), 128>>>(gw + h * 2048, gb + h * 128,
                                    gg + h * 128, gbe + h * 128, out, h == 0 ? 1 : 0);
    }
}

// round 12
// speedup vs baseline: 1.1262x; 1.0827x over previous
#include <cuda_runtime.h>
#include <cuda_bf16.h>
#include <math.h>
#include <stdint.h>

#define VN    8192
#define NCOL  64
#define KA    72            // smem row stride in bf16 (144B, LDSM conflict-free)

// smem plane byte offsets within one buffer (M-tile 64, k-tile 64)
#define AHI_OFF 0
#define ALO_OFF 9216        // 64*72*2
#define BHI_OFF 18432
#define BLO_OFF 27648
#define BUFSZ   36864
#define STAGES  3
#define DSMEM_GEMM (STAGES*BUFSZ)   // 110592

// ---------------- device scratch ---------------------------------------------
__device__ __nv_bfloat16 g_adjh[(size_t)VN * VN];   // blended adj, bf16 hi
__device__ __nv_bfloat16 g_adjl[(size_t)VN * VN];   // bf16 lo residual
__device__ float g_rowsum[VN];
__device__ float g_part[2][(size_t)VN * NCOL];
__device__ float g_X[(size_t)VN * NCOL];            // hop output [v][col]
__device__ __nv_bfloat16 g_XTh[(size_t)NCOL * VN];  // B operand, split, [col][w]
__device__ __nv_bfloat16 g_XTl[(size_t)NCOL * VN];
__device__ float g_M[64 * 256];                     // x xT partials [sblk][16*16]
__device__ float g_S[64 * 16];                      // x partials   [sblk][16]

// ---------------- helpers ------------------------------------------------------
__device__ __forceinline__ uint32_t smem_u32(const void* p) {
    uint32_t a;
    asm("{ .reg .u64 t; cvta.to.shared.u64 t, %1; cvt.u32.u64 %0, t; }" : "=r"(a) : "l"(p));
    return a;
}
__device__ __forceinline__ void bsplit(float x, float y, uint32_t& hi, uint32_t& lo) {
    __nv_bfloat162 h = __floats2bfloat162_rn(x, y);
    float hx = __bfloat162float(h.x), hy = __bfloat162float(h.y);
    __nv_bfloat162 l = __floats2bfloat162_rn(x - hx, y - hy);
    hi = *reinterpret_cast<uint32_t*>(&h);
    lo = *reinterpret_cast<uint32_t*>(&l);
}
__device__ __forceinline__ void mma_bf16(float* c,
    uint32_t a0, uint32_t a1, uint32_t a2, uint32_t a3, uint32_t b0, uint32_t b1) {
    asm volatile(
        "mma.sync.aligned.m16n8k16.row.col.f32.bf16.bf16.f32 "
        "{%0,%1,%2,%3}, {%4,%5,%6,%7}, {%8,%9}, {%0,%1,%2,%3};"
        : "+f"(c[0]), "+f"(c[1]), "+f"(c[2]), "+f"(c[3])
        : "r"(a0), "r"(a1), "r"(a2), "r"(a3), "r"(b0), "r"(b1));
}
__device__ __forceinline__ void ldsm4(uint32_t addr, uint32_t* r) {
    asm volatile("ldmatrix.sync.aligned.m8n8.x4.shared.b16 {%0,%1,%2,%3}, [%4];"
        : "=r"(r[0]), "=r"(r[1]), "=r"(r[2]), "=r"(r[3]) : "r"(addr));
}
__device__ __forceinline__ void cpa16(uint32_t dst, const void* src) {
    asm volatile("cp.async.cg.shared.global [%0], [%1], 16;" :: "r"(dst), "l"(src) : "memory");
}
#define CP_COMMIT() asm volatile("cp.async.commit_group;" ::: "memory")

// one 64x64x64 k-tile; warp = 16 rows x 32 cols, 3-term bf16 split (chained acc)
__device__ __forceinline__ void mma_tile(uint32_t base, float acc[4][4],
                                         uint32_t aoff, const uint32_t* boff) {
#pragma unroll
    for (int ks = 0; ks < 4; ++ks) {
        const uint32_t kb = ks * 32;
        uint32_t ah[4], al[4];
        ldsm4(base + AHI_OFF + aoff + kb, ah);
        ldsm4(base + ALO_OFF + aoff + kb, al);
#pragma unroll
        for (int g = 0; g < 2; ++g) {
            uint32_t bh[4], bl[4];
            ldsm4(base + BHI_OFF + boff[g] + kb, bh);
            ldsm4(base + BLO_OFF + boff[g] + kb, bl);
            mma_bf16(acc[2*g],   ah[0],ah[1],ah[2],ah[3], bh[0],bh[1]);
            mma_bf16(acc[2*g],   ah[0],ah[1],ah[2],ah[3], bl[0],bl[1]);
            mma_bf16(acc[2*g],   al[0],al[1],al[2],al[3], bh[0],bh[1]);
            mma_bf16(acc[2*g+1], ah[0],ah[1],ah[2],ah[3], bh[2],bh[3]);
            mma_bf16(acc[2*g+1], ah[0],ah[1],ah[2],ah[3], bl[2],bl[3]);
            mma_bf16(acc[2*g+1], al[0],al[1],al[2],al[3], bh[2],bh[3]);
        }
    }
}

// warp layout: rw = wid>>1 (M group of 16), cw = wid&1 (N group of 32)
__device__ __forceinline__ void frag_offsets(int lane, int wid, uint32_t& aoff, uint32_t* boff) {
    const int rr = lane & 7, sel = lane >> 3;
    const int rw = wid >> 1, cw = wid & 1;
    aoff = ((rw * 16 + (sel & 1) * 8 + rr) * KA + (sel >> 1) * 8) * 2;
#pragma unroll
    for (int g = 0; g < 2; ++g)
        boff[g] = ((cw * 32 + g * 16 + (sel >> 1) * 8 + rr) * KA + (sel & 1) * 8) * 2;
}

__device__ __forceinline__ void write_partials(float acc[4][4], int s, int vbase,
                                               int wid, int lane) {
    const int rw = wid >> 1, cw = wid & 1;
    float* dst = g_part[s] + (size_t)(vbase + rw * 16) * NCOL + cw * 32;
    const int gr = lane >> 2, cq = (lane & 3) * 2;
#pragma unroll
    for (int nb = 0; nb < 4; ++nb) {
        const int col = nb * 8 + cq;
        *(float2*)(dst + (size_t)gr * NCOL + col)       = make_float2(acc[nb][0], acc[nb][1]);
        *(float2*)(dst + (size_t)(gr + 8) * NCOL + col) = make_float2(acc[nb][2], acc[nb][3]);
    }
}

// ---------------- prep: data -> split transposed B ([col][w]) -----------------
__global__ __launch_bounds__(256) void k_prepB(const float* __restrict__ data) {
    int fidx = blockIdx.x * 256 + threadIdx.x;   // 131072 float4s
    int col = fidx >> 11;
    int w4  = (fidx & 2047) << 2;
    float4 v = *(const float4*)(data + (size_t)col * 16384 + w4);
    uint32_t h0, l0, h1, l1;
    bsplit(v.x, v.y, h0, l0);
    bsplit(v.z, v.w, h1, l1);
    *reinterpret_cast<uint2*>(g_XTh + (size_t)col * VN + w4) = make_uint2(h0, h1);
    *reinterpret_cast<uint2*>(g_XTl + (size_t)col * VN + w4) = make_uint2(l0, l1);
}

// ---------------- blend: 5-stream -> split bf16 planes + rowsum ---------------
__global__ __launch_bounds__(256) void k_blend(
    const float* __restrict__ adjf, const float* __restrict__ adjs,
    const float* __restrict__ adjm,
    const float* __restrict__ alf, const float* __restrict__ als)
{
    const float e0 = expf(alf[0]), e1 = expf(alf[1]);
    const float f0 = expf(als[0]), f1 = expf(als[1]);
    const float w0 = e0 / (e0 + e1), w1 = e1 / (e0 + e1);
    const float w2 = f0 / (f0 + f1), w3 = f1 / (f0 + f1);

    const int wid = threadIdx.x >> 5, lane = threadIdx.x & 31;
    const int row = blockIdx.x * 8 + wid;
    const size_t base = (size_t)row * VN;
    const float* __restrict__ a0 = adjf + base;
    const float* __restrict__ a1 = adjf + (size_t)VN * VN + base;
    const float* __restrict__ b0 = adjs + base;
    const float* __restrict__ b1 = adjs + (size_t)VN * VN + base;
    const float* __restrict__ m0 = adjm + base;
    __nv_bfloat16* __restrict__ dh = g_adjh + base;
    __nv_bfloat16* __restrict__ dl = g_adjl + base;
    float rs = 0.f;
    for (int i = lane; i < 2048; i += 64) {
#pragma unroll
        for (int u = 0; u < 2; ++u) {
            const int o4 = (i + u * 32) * 4;
            float4 a = *(const float4*)(a0 + o4);
            float4 b = *(const float4*)(a1 + o4);
            float4 c = *(const float4*)(b0 + o4);
            float4 d = *(const float4*)(b1 + o4);
            float4 m = *(const float4*)(m0 + o4);
            float4 r;
            r.x = fmaf(w0, a.x, fmaf(w1, b.x, fmaf(w2, c.x, fmaf(w3, d.x, m.x))));
            r.y = fmaf(w0, a.y, fmaf(w1, b.y, fmaf(w2, c.y, fmaf(w3, d.y, m.y))));
            r.z = fmaf(w0, a.z, fmaf(w1, b.z, fmaf(w2, c.z, fmaf(w3, d.z, m.z))));
            r.w = fmaf(w0, a.w, fmaf(w1, b.w, fmaf(w2, c.w, fmaf(w3, d.w, m.w))));
            rs += (r.x + r.y) + (r.z + r.w);
            uint32_t h0, l0, h1, l1;
            bsplit(r.x, r.y, h0, l0);
            bsplit(r.z, r.w, h1, l1);
            *reinterpret_cast<uint2*>(dh + o4) = make_uint2(h0, h1);
            *reinterpret_cast<uint2*>(dl + o4) = make_uint2(l0, l1);
        }
    }
    rs += __shfl_xor_sync(0xffffffffu, rs, 16);
    rs += __shfl_xor_sync(0xffffffffu, rs, 8);
    rs += __shfl_xor_sync(0xffffffffu, rs, 4);
    rs += __shfl_xor_sync(0xffffffffu, rs, 2);
    rs += __shfl_xor_sync(0xffffffffu, rs, 1);
    if (lane == 0) g_rowsum[row] = rs;
}

// ---------------- hop GEMM: 3-stage cp.async, ONE barrier per tile ------------
__global__ __launch_bounds__(256, 2) void k_gemm()
{
    extern __shared__ __align__(16) char smem[];
    const uint32_t base = smem_u32(smem);
    const int tid = threadIdx.x, lane = tid & 31, wid = tid >> 5;
    const int vbase = blockIdx.x * 64;
    const int kbase = blockIdx.y * 4096;

    uint32_t aoff, boff[2];
    frag_offsets(lane, wid, aoff, boff);

    float acc[4][4];
#pragma unroll
    for (int i = 0; i < 4; ++i)
#pragma unroll
        for (int j = 0; j < 4; ++j) acc[i][j] = 0.f;

    auto issue = [&](int t) {
        const uint32_t dst = base + (uint32_t)(t % STAGES) * BUFSZ;
        const int kg = kbase + t * 64;
#pragma unroll
        for (int j = 0; j < 2; ++j) {
            const int id = tid + 256 * j;
            const int row = id >> 3, ch = id & 7;
            const size_t go = (size_t)(vbase + row) * VN + kg + ch * 8;
            const uint32_t so = (uint32_t)(row * KA + ch * 8) * 2;
            cpa16(dst + AHI_OFF + so, g_adjh + go);
            cpa16(dst + ALO_OFF + so, g_adjl + go);
        }
#pragma unroll
        for (int j = 0; j < 2; ++j) {
            const int id = tid + 256 * j;
            const int n = id >> 3, ch = id & 7;
            const size_t go = (size_t)n * VN + kg + ch * 8;
            const uint32_t so = (uint32_t)(n * KA + ch * 8) * 2;
            cpa16(dst + BHI_OFF + so, g_XTh + go);
            cpa16(dst + BLO_OFF + so, g_XTl + go);
        }
        CP_COMMIT();
    };

    issue(0); issue(1);
    for (int t = 0; t < 64; ++t) {
        if (t < 63) asm volatile("cp.async.wait_group 1;" ::: "memory");
        else        asm volatile("cp.async.wait_group 0;" ::: "memory");
        __syncthreads();
        mma_tile(base + (uint32_t)(t % STAGES) * BUFSZ, acc, aoff, boff);
        if (t + 2 < 64) issue(t + 2);
    }

    write_partials(acc, blockIdx.y, vbase, wid, lane);
}

// ---------------- combine + second-moment BN partials --------------------------
// normalizes partials -> g_X; upper blocks emit M = sum(x x^T), S = sum(x)
// over their 256 staged points (64 rows x 4 batches). Transpose-split B
// skipped on last hop.
__global__ __launch_bounds__(256) void k_combine(int lastHop) {
    __shared__ float sm[64][65];
    __shared__ float rs[64];
    const int tid = threadIdx.x;
    const int vbase = blockIdx.x * 64;
    if (tid < 64) rs[tid] = g_rowsum[vbase + tid];
    __syncthreads();
#pragma unroll
    for (int j = 0; j < 4; ++j) {
        const int f = tid + j * 256;
        const int r = f >> 4, c = (f & 15) << 2;
        const size_t o = (size_t)(vbase + r) * NCOL + c;
        float4 p = *(const float4*)(g_part[0] + o);
        float4 q = *(const float4*)(g_part[1] + o);
        const float inv = 1.f / rs[r];
        float4 v;
        v.x = (p.x + q.x) * inv; v.y = (p.y + q.y) * inv;
        v.z = (p.z + q.z) * inv; v.w = (p.w + q.w) * inv;
        *(float4*)(g_X + o) = v;
        sm[r][c] = v.x; sm[r][c + 1] = v.y; sm[r][c + 2] = v.z; sm[r][c + 3] = v.w;
    }
    __syncthreads();
    if (!lastHop) {
        const int col = tid >> 2;
        const int v0 = (tid & 3) << 4;
#pragma unroll
        for (int j = 0; j < 4; ++j) {
            const int v = v0 + j * 4;
            float4 x;
            x.x = sm[v][col]; x.y = sm[v + 1][col]; x.z = sm[v + 2][col]; x.w = sm[v + 3][col];
            uint32_t h0, l0, h1, l1;
            bsplit(x.x, x.y, h0, l0);
            bsplit(x.z, x.w, h1, l1);
            *reinterpret_cast<uint2*>(g_XTh + (size_t)col * VN + vbase + v) = make_uint2(h0, h1);
            *reinterpret_cast<uint2*>(g_XTl + (size_t)col * VN + vbase + v) = make_uint2(l0, l1);
        }
    }
    // second-moment partials for the GLU segment (rows 4096..8191)
    if (vbase >= 4096) {
        const int i = tid >> 4, jj = tid & 15;
        float mij = 0.f, si = 0.f;
        for (int r = 0; r < 64; ++r) {
#pragma unroll
            for (int b = 0; b < 4; ++b) {
                const float xi = sm[r][b * 16 + i];
                const float xj = sm[r][b * 16 + jj];
                mij = fmaf(xi, xj, mij);
                if (jj == 0) si += xi;
            }
        }
        const int sblk = blockIdx.x - 64;
        g_M[sblk * 256 + tid] = mij;
        if (jj == 0) g_S[sblk * 16 + i] = si;
    }
}

// ---------------- GLU + BN apply (stats via quadratic form) -------------------
__global__ __launch_bounds__(128) void k_glu(const float* __restrict__ W,
    const float* __restrict__ bias, const float* __restrict__ gamma,
    const float* __restrict__ beta, float* __restrict__ out, int first)
{
    __shared__ float Wsm[2048], bsm[128], gsm[128], besm[128], musm[128], rsm[128];
    __shared__ float Msm[256], Ssm[16];
    const int tid = threadIdx.x;
    const int n = blockIdx.x * 128 + tid;
    const int b = blockIdx.y;
#pragma unroll
    for (int j = 0; j < 16; ++j) Wsm[tid * 16 + j] = W[tid * 16 + j];
    bsm[tid] = bias[tid]; gsm[tid] = gamma[tid]; besm[tid] = beta[tid];
    {   // reduce M/S partials over 64 blocks (L2-resident)
        float m0 = 0.f, m1 = 0.f;
        for (int k = 0; k < 64; ++k) {
            m0 += g_M[k * 256 + tid];
            m1 += g_M[k * 256 + 128 + tid];
        }
        Msm[tid] = m0; Msm[128 + tid] = m1;
        if (tid < 16) {
            float s = 0.f;
            for (int k = 0; k < 64; ++k) s += g_S[k * 16 + tid];
            Ssm[tid] = s;
        }
    }
    __syncthreads();
    {   // per-channel stats from quadratic form
        const float* w = &Wsm[tid * 16];
        const float bb = bsm[tid];
        float q = 0.f, sw = 0.f;
#pragma unroll
        for (int i = 0; i < 16; ++i) {
            const float wi = w[i];
            sw = fmaf(wi, Ssm[i], sw);
            float row = 0.f;
#pragma unroll
            for (int j = 0; j < 16; ++j) row = fmaf(w[j], Msm[i * 16 + j], row);
            q = fmaf(wi, row, q);
        }
        const float N = 16384.f, invN = 1.f / 16384.f;
        const float mu = (sw + N * bb) * invN;
        const float ey2 = (q + 2.f * bb * sw + N * bb * bb) * invN;
        musm[tid] = mu;
        rsm[tid] = rsqrtf(ey2 - mu * mu + 1e-5f);
    }
    __syncthreads();

    float xr[16];
    const float* __restrict__ xp = g_X + (size_t)4096 * NCOL + (size_t)n * 64 + b * 16;
#pragma unroll
    for (int j = 0; j < 4; ++j) {
        float4 t = *(const float4*)(xp + j * 4);
        xr[j * 4] = t.x; xr[j * 4 + 1] = t.y; xr[j * 4 + 2] = t.z; xr[j * 4 + 3] = t.w;
    }
    float* op = out + (size_t)b * (64 * 4096) + n;
    for (int f = 0; f < 64; ++f) {
        const float* wl = &Wsm[f * 16];
        const float* wr = &Wsm[(f + 64) * 16];
        float yl = bsm[f], yr = bsm[f + 64];
#pragma unroll
        for (int c = 0; c < 16; ++c) {
            yl = fmaf(wl[c], xr[c], yl);
            yr = fmaf(wr[c], xr[c], yr);
        }
        yl = fmaf(gsm[f] * (yl - musm[f]), rsm[f], besm[f]);
        yr = fmaf(gsm[f + 64] * (yr - musm[f + 64]), rsm[f + 64], besm[f + 64]);
        float val = yl / (1.f + expf(-yr));
        float* po = op + (size_t)f * 4096;
        if (first) *po = val;
        else       *po = fmaxf(*po, val);
    }
}

// ---------------- launch -----------------------------------------------------
extern "C" void kernel_launch(void* const* d_in, const int* in_sizes, int n_in,
                              void* d_out, int out_size)
{
    (void)in_sizes; (void)n_in; (void)out_size;
    const float* adjf = (const float*)d_in[0];
    const float* adjs = (const float*)d_in[1];
    const float* adjm = (const float*)d_in[2];
    const float* data = (const float*)d_in[3];
    const float* alf  = (const float*)d_in[4];
    const float* als  = (const float*)d_in[5];
    const float* gw   = (const float*)d_in[6];
    const float* gb   = (const float*)d_in[7];
    const float* gg   = (const float*)d_in[8];
    const float* gbe  = (const float*)d_in[9];
    float* out = (float*)d_out;

    cudaFuncSetAttribute(k_gemm, cudaFuncAttributeMaxDynamicSharedMemorySize, DSMEM_GEMM);

    k_prepB<<<512, 256>>>(data);
    k_blend<<<1024, 256>>>(adjf, adjs, adjm, alf, als);

    for (int h = 0; h < 3; ++h) {
        k_gemm<<<dim3(128, 2), 256, DSMEM_GEMM>>>();
        k_combine<<<128, 256>>>(h == 2 ? 1 : 0);
        k_glu<<<dim3(32, 4), 128>>>(gw + h * 2048, gb + h * 128,
                                    gg + h * 128, gbe + h * 128, out, h == 0 ? 1 : 0);
    }
}

// round 13
// speedup vs baseline: 1.1830x; 1.0505x over previous
#include <cuda_runtime.h>
#include <cuda_bf16.h>
#include <math.h>
#include <stdint.h>

#define VN    8192
#define NCOL  64
#define KA    72            // smem row stride in bf16 (144B, LDSM conflict-free)

// smem plane byte offsets within one buffer (M-tile 64, k-tile 64)
#define AHI_OFF 0
#define ALO_OFF 9216        // 64*72*2
#define BHI_OFF 18432
#define BLO_OFF 27648
#define BUFSZ   36864
#define STAGES  3
#define DSMEM_GEMM (STAGES*BUFSZ)   // 110592

// ---------------- device scratch ---------------------------------------------
__device__ __nv_bfloat16 g_adjh[(size_t)VN * VN];   // blended adj, bf16 hi
__device__ __nv_bfloat16 g_adjl[(size_t)VN * VN];   // bf16 lo residual
__device__ float g_rowsum[VN];
__device__ float g_part[2][(size_t)VN * NCOL];
__device__ float g_X[(size_t)VN * NCOL];            // hop output [v][col]
__device__ __nv_bfloat16 g_XTh[(size_t)NCOL * VN];  // B operand, split, [col][w]
__device__ __nv_bfloat16 g_XTl[(size_t)NCOL * VN];
__device__ float g_M[64 * 256];                     // x xT partials [sblk][16*16]
__device__ float g_S[64 * 16];                      // x partials   [sblk][16]

// ---------------- helpers ------------------------------------------------------
__device__ __forceinline__ uint32_t smem_u32(const void* p) {
    uint32_t a;
    asm("{ .reg .u64 t; cvta.to.shared.u64 t, %1; cvt.u32.u64 %0, t; }" : "=r"(a) : "l"(p));
    return a;
}
__device__ __forceinline__ void bsplit(float x, float y, uint32_t& hi, uint32_t& lo) {
    __nv_bfloat162 h = __floats2bfloat162_rn(x, y);
    float hx = __bfloat162float(h.x), hy = __bfloat162float(h.y);
    __nv_bfloat162 l = __floats2bfloat162_rn(x - hx, y - hy);
    hi = *reinterpret_cast<uint32_t*>(&h);
    lo = *reinterpret_cast<uint32_t*>(&l);
}
__device__ __forceinline__ void mma_bf16(float* c,
    uint32_t a0, uint32_t a1, uint32_t a2, uint32_t a3, uint32_t b0, uint32_t b1) {
    asm volatile(
        "mma.sync.aligned.m16n8k16.row.col.f32.bf16.bf16.f32 "
        "{%0,%1,%2,%3}, {%4,%5,%6,%7}, {%8,%9}, {%0,%1,%2,%3};"
        : "+f"(c[0]), "+f"(c[1]), "+f"(c[2]), "+f"(c[3])
        : "r"(a0), "r"(a1), "r"(a2), "r"(a3), "r"(b0), "r"(b1));
}
__device__ __forceinline__ void ldsm4(uint32_t addr, uint32_t* r) {
    asm volatile("ldmatrix.sync.aligned.m8n8.x4.shared.b16 {%0,%1,%2,%3}, [%4];"
        : "=r"(r[0]), "=r"(r[1]), "=r"(r[2]), "=r"(r[3]) : "r"(addr));
}
__device__ __forceinline__ void cpa16(uint32_t dst, const void* src) {
    asm volatile("cp.async.cg.shared.global [%0], [%1], 16;" :: "r"(dst), "l"(src) : "memory");
}
#define CP_COMMIT() asm volatile("cp.async.commit_group;" ::: "memory")

// one 64x64x64 k-tile; warp = 16 rows x 32 cols, 3-term bf16 split (chained acc)
__device__ __forceinline__ void mma_tile(uint32_t base, float acc[4][4],
                                         uint32_t aoff, const uint32_t* boff) {
#pragma unroll
    for (int ks = 0; ks < 4; ++ks) {
        const uint32_t kb = ks * 32;
        uint32_t ah[4], al[4];
        ldsm4(base + AHI_OFF + aoff + kb, ah);
        ldsm4(base + ALO_OFF + aoff + kb, al);
#pragma unroll
        for (int g = 0; g < 2; ++g) {
            uint32_t bh[4], bl[4];
            ldsm4(base + BHI_OFF + boff[g] + kb, bh);
            ldsm4(base + BLO_OFF + boff[g] + kb, bl);
            mma_bf16(acc[2*g],   ah[0],ah[1],ah[2],ah[3], bh[0],bh[1]);
            mma_bf16(acc[2*g],   ah[0],ah[1],ah[2],ah[3], bl[0],bl[1]);
            mma_bf16(acc[2*g],   al[0],al[1],al[2],al[3], bh[0],bh[1]);
            mma_bf16(acc[2*g+1], ah[0],ah[1],ah[2],ah[3], bh[2],bh[3]);
            mma_bf16(acc[2*g+1], ah[0],ah[1],ah[2],ah[3], bl[2],bl[3]);
            mma_bf16(acc[2*g+1], al[0],al[1],al[2],al[3], bh[2],bh[3]);
        }
    }
}

// warp layout: rw = wid>>1 (M group of 16), cw = wid&1 (N group of 32)
__device__ __forceinline__ void frag_offsets(int lane, int wid, uint32_t& aoff, uint32_t* boff) {
    const int rr = lane & 7, sel = lane >> 3;
    const int rw = wid >> 1, cw = wid & 1;
    aoff = ((rw * 16 + (sel & 1) * 8 + rr) * KA + (sel >> 1) * 8) * 2;
#pragma unroll
    for (int g = 0; g < 2; ++g)
        boff[g] = ((cw * 32 + g * 16 + (sel >> 1) * 8 + rr) * KA + (sel & 1) * 8) * 2;
}

__device__ __forceinline__ void write_partials(float acc[4][4], int s, int vbase,
                                               int wid, int lane) {
    const int rw = wid >> 1, cw = wid & 1;
    float* dst = g_part[s] + (size_t)(vbase + rw * 16) * NCOL + cw * 32;
    const int gr = lane >> 2, cq = (lane & 3) * 2;
#pragma unroll
    for (int nb = 0; nb < 4; ++nb) {
        const int col = nb * 8 + cq;
        *(float2*)(dst + (size_t)gr * NCOL + col)       = make_float2(acc[nb][0], acc[nb][1]);
        *(float2*)(dst + (size_t)(gr + 8) * NCOL + col) = make_float2(acc[nb][2], acc[nb][3]);
    }
}

// ---------------- prep: data -> split transposed B ([col][w]) -----------------
__global__ __launch_bounds__(256) void k_prepB(const float* __restrict__ data) {
    int fidx = blockIdx.x * 256 + threadIdx.x;   // 131072 float4s
    int col = fidx >> 11;
    int w4  = (fidx & 2047) << 2;
    float4 v = *(const float4*)(data + (size_t)col * 16384 + w4);
    uint32_t h0, l0, h1, l1;
    bsplit(v.x, v.y, h0, l0);
    bsplit(v.z, v.w, h1, l1);
    *reinterpret_cast<uint2*>(g_XTh + (size_t)col * VN + w4) = make_uint2(h0, h1);
    *reinterpret_cast<uint2*>(g_XTl + (size_t)col * VN + w4) = make_uint2(l0, l1);
}

// ---------------- blend: 5-stream -> split bf16 planes + rowsum ---------------
__global__ __launch_bounds__(256) void k_blend(
    const float* __restrict__ adjf, const float* __restrict__ adjs,
    const float* __restrict__ adjm,
    const float* __restrict__ alf, const float* __restrict__ als)
{
    const float e0 = expf(alf[0]), e1 = expf(alf[1]);
    const float f0 = expf(als[0]), f1 = expf(als[1]);
    const float w0 = e0 / (e0 + e1), w1 = e1 / (e0 + e1);
    const float w2 = f0 / (f0 + f1), w3 = f1 / (f0 + f1);

    const int wid = threadIdx.x >> 5, lane = threadIdx.x & 31;
    const int row = blockIdx.x * 8 + wid;
    const size_t base = (size_t)row * VN;
    const float* __restrict__ a0 = adjf + base;
    const float* __restrict__ a1 = adjf + (size_t)VN * VN + base;
    const float* __restrict__ b0 = adjs + base;
    const float* __restrict__ b1 = adjs + (size_t)VN * VN + base;
    const float* __restrict__ m0 = adjm + base;
    __nv_bfloat16* __restrict__ dh = g_adjh + base;
    __nv_bfloat16* __restrict__ dl = g_adjl + base;
    float rs = 0.f;
    for (int i = lane; i < 2048; i += 64) {
#pragma unroll
        for (int u = 0; u < 2; ++u) {
            const int o4 = (i + u * 32) * 4;
            float4 a = *(const float4*)(a0 + o4);
            float4 b = *(const float4*)(a1 + o4);
            float4 c = *(const float4*)(b0 + o4);
            float4 d = *(const float4*)(b1 + o4);
            float4 m = *(const float4*)(m0 + o4);
            float4 r;
            r.x = fmaf(w0, a.x, fmaf(w1, b.x, fmaf(w2, c.x, fmaf(w3, d.x, m.x))));
            r.y = fmaf(w0, a.y, fmaf(w1, b.y, fmaf(w2, c.y, fmaf(w3, d.y, m.y))));
            r.z = fmaf(w0, a.z, fmaf(w1, b.z, fmaf(w2, c.z, fmaf(w3, d.z, m.z))));
            r.w = fmaf(w0, a.w, fmaf(w1, b.w, fmaf(w2, c.w, fmaf(w3, d.w, m.w))));
            rs += (r.x + r.y) + (r.z + r.w);
            uint32_t h0, l0, h1, l1;
            bsplit(r.x, r.y, h0, l0);
            bsplit(r.z, r.w, h1, l1);
            *reinterpret_cast<uint2*>(dh + o4) = make_uint2(h0, h1);
            *reinterpret_cast<uint2*>(dl + o4) = make_uint2(l0, l1);
        }
    }
    rs += __shfl_xor_sync(0xffffffffu, rs, 16);
    rs += __shfl_xor_sync(0xffffffffu, rs, 8);
    rs += __shfl_xor_sync(0xffffffffu, rs, 4);
    rs += __shfl_xor_sync(0xffffffffu, rs, 2);
    rs += __shfl_xor_sync(0xffffffffu, rs, 1);
    if (lane == 0) g_rowsum[row] = rs;
}

// ---------------- hop GEMM: 3-stage cp.async, ONE barrier per tile ------------
// grid (Mtiles, 2): vstart + 64-row M tiles x split-K halves. 64 k-tiles/CTA.
__global__ __launch_bounds__(256, 2) void k_gemm(int vstart)
{
    extern __shared__ __align__(16) char smem[];
    const uint32_t base = smem_u32(smem);
    const int tid = threadIdx.x, lane = tid & 31, wid = tid >> 5;
    const int vbase = vstart + blockIdx.x * 64;
    const int kbase = blockIdx.y * 4096;

    uint32_t aoff, boff[2];
    frag_offsets(lane, wid, aoff, boff);

    float acc[4][4];
#pragma unroll
    for (int i = 0; i < 4; ++i)
#pragma unroll
        for (int j = 0; j < 4; ++j) acc[i][j] = 0.f;

    auto issue = [&](int t) {
        const uint32_t dst = base + (uint32_t)(t % STAGES) * BUFSZ;
        const int kg = kbase + t * 64;
#pragma unroll
        for (int j = 0; j < 2; ++j) {
            const int id = tid + 256 * j;
            const int row = id >> 3, ch = id & 7;
            const size_t go = (size_t)(vbase + row) * VN + kg + ch * 8;
            const uint32_t so = (uint32_t)(row * KA + ch * 8) * 2;
            cpa16(dst + AHI_OFF + so, g_adjh + go);
            cpa16(dst + ALO_OFF + so, g_adjl + go);
        }
#pragma unroll
        for (int j = 0; j < 2; ++j) {
            const int id = tid + 256 * j;
            const int n = id >> 3, ch = id & 7;
            const size_t go = (size_t)n * VN + kg + ch * 8;
            const uint32_t so = (uint32_t)(n * KA + ch * 8) * 2;
            cpa16(dst + BHI_OFF + so, g_XTh + go);
            cpa16(dst + BLO_OFF + so, g_XTl + go);
        }
        CP_COMMIT();
    };

    issue(0); issue(1);
    for (int t = 0; t < 64; ++t) {
        if (t < 63) asm volatile("cp.async.wait_group 1;" ::: "memory");
        else        asm volatile("cp.async.wait_group 0;" ::: "memory");
        __syncthreads();
        mma_tile(base + (uint32_t)(t % STAGES) * BUFSZ, acc, aoff, boff);
        if (t + 2 < 64) issue(t + 2);
    }

    write_partials(acc, blockIdx.y, vbase, wid, lane);
}

// ---------------- combine + second-moment BN partials --------------------------
// normalizes partials -> g_X; blocks with vbase>=4096 emit M = sum(x x^T),
// S = sum(x). Transpose-split B skipped on last hop.
__global__ __launch_bounds__(256) void k_combine(int vstart, int lastHop) {
    __shared__ float sm[64][65];
    __shared__ float rs[64];
    const int tid = threadIdx.x;
    const int vbase = vstart + blockIdx.x * 64;
    if (tid < 64) rs[tid] = g_rowsum[vbase + tid];
    __syncthreads();
#pragma unroll
    for (int j = 0; j < 4; ++j) {
        const int f = tid + j * 256;
        const int r = f >> 4, c = (f & 15) << 2;
        const size_t o = (size_t)(vbase + r) * NCOL + c;
        float4 p = *(const float4*)(g_part[0] + o);
        float4 q = *(const float4*)(g_part[1] + o);
        const float inv = 1.f / rs[r];
        float4 v;
        v.x = (p.x + q.x) * inv; v.y = (p.y + q.y) * inv;
        v.z = (p.z + q.z) * inv; v.w = (p.w + q.w) * inv;
        *(float4*)(g_X + o) = v;
        sm[r][c] = v.x; sm[r][c + 1] = v.y; sm[r][c + 2] = v.z; sm[r][c + 3] = v.w;
    }
    __syncthreads();
    if (!lastHop) {
        const int col = tid >> 2;
        const int v0 = (tid & 3) << 4;
#pragma unroll
        for (int j = 0; j < 4; ++j) {
            const int v = v0 + j * 4;
            float4 x;
            x.x = sm[v][col]; x.y = sm[v + 1][col]; x.z = sm[v + 2][col]; x.w = sm[v + 3][col];
            uint32_t h0, l0, h1, l1;
            bsplit(x.x, x.y, h0, l0);
            bsplit(x.z, x.w, h1, l1);
            *reinterpret_cast<uint2*>(g_XTh + (size_t)col * VN + vbase + v) = make_uint2(h0, h1);
            *reinterpret_cast<uint2*>(g_XTl + (size_t)col * VN + vbase + v) = make_uint2(l0, l1);
        }
    }
    // second-moment partials for the GLU segment (rows 4096..8191)
    if (vbase >= 4096) {
        const int i = tid >> 4, jj = tid & 15;
        float mij = 0.f, si = 0.f;
        for (int r = 0; r < 64; ++r) {
#pragma unroll
            for (int b = 0; b < 4; ++b) {
                const float xi = sm[r][b * 16 + i];
                const float xj = sm[r][b * 16 + jj];
                mij = fmaf(xi, xj, mij);
                if (jj == 0) si += xi;
            }
        }
        const int sblk = (vbase - 4096) >> 6;
        g_M[sblk * 256 + tid] = mij;
        if (jj == 0) g_S[sblk * 16 + i] = si;
    }
}

// ---------------- GLU + BN apply (stats via quadratic form) -------------------
__global__ __launch_bounds__(128) void k_glu(const float* __restrict__ W,
    const float* __restrict__ bias, const float* __restrict__ gamma,
    const float* __restrict__ beta, float* __restrict__ out, int first)
{
    __shared__ float Wsm[2048], bsm[128], gsm[128], besm[128], musm[128], rsm[128];
    __shared__ float Msm[256], Ssm[16];
    const int tid = threadIdx.x;
    const int n = blockIdx.x * 128 + tid;
    const int b = blockIdx.y;
#pragma unroll
    for (int j = 0; j < 16; ++j) Wsm[tid * 16 + j] = W[tid * 16 + j];
    bsm[tid] = bias[tid]; gsm[tid] = gamma[tid]; besm[tid] = beta[tid];
    {   // reduce M/S partials over 64 blocks (L2-resident)
        float m0 = 0.f, m1 = 0.f;
        for (int k = 0; k < 64; ++k) {
            m0 += g_M[k * 256 + tid];
            m1 += g_M[k * 256 + 128 + tid];
        }
        Msm[tid] = m0; Msm[128 + tid] = m1;
        if (tid < 16) {
            float s = 0.f;
            for (int k = 0; k < 64; ++k) s += g_S[k * 16 + tid];
            Ssm[tid] = s;
        }
    }
    __syncthreads();
    {   // per-channel stats from quadratic form
        const float* w = &Wsm[tid * 16];
        const float bb = bsm[tid];
        float q = 0.f, sw = 0.f;
#pragma unroll
        for (int i = 0; i < 16; ++i) {
            const float wi = w[i];
            sw = fmaf(wi, Ssm[i], sw);
            float row = 0.f;
#pragma unroll
            for (int j = 0; j < 16; ++j) row = fmaf(w[j], Msm[i * 16 + j], row);
            q = fmaf(wi, row, q);
        }
        const float N = 16384.f, invN = 1.f / 16384.f;
        const float mu = (sw + N * bb) * invN;
        const float ey2 = (q + 2.f * bb * sw + N * bb * bb) * invN;
        musm[tid] = mu;
        rsm[tid] = rsqrtf(ey2 - mu * mu + 1e-5f);
    }
    __syncthreads();

    float xr[16];
    const float* __restrict__ xp = g_X + (size_t)4096 * NCOL + (size_t)n * 64 + b * 16;
#pragma unroll
    for (int j = 0; j < 4; ++j) {
        float4 t = *(const float4*)(xp + j * 4);
        xr[j * 4] = t.x; xr[j * 4 + 1] = t.y; xr[j * 4 + 2] = t.z; xr[j * 4 + 3] = t.w;
    }
    float* op = out + (size_t)b * (64 * 4096) + n;
    for (int f = 0; f < 64; ++f) {
        const float* wl = &Wsm[f * 16];
        const float* wr = &Wsm[(f + 64) * 16];
        float yl = bsm[f], yr = bsm[f + 64];
#pragma unroll
        for (int c = 0; c < 16; ++c) {
            yl = fmaf(wl[c], xr[c], yl);
            yr = fmaf(wr[c], xr[c], yr);
        }
        yl = fmaf(gsm[f] * (yl - musm[f]), rsm[f], besm[f]);
        yr = fmaf(gsm[f + 64] * (yr - musm[f + 64]), rsm[f + 64], besm[f + 64]);
        float val = yl / (1.f + expf(-yr));
        float* po = op + (size_t)f * 4096;
        if (first) *po = val;
        else       *po = fmaxf(*po, val);
    }
}

// ---------------- launch -----------------------------------------------------
extern "C" void kernel_launch(void* const* d_in, const int* in_sizes, int n_in,
                              void* d_out, int out_size)
{
    (void)in_sizes; (void)n_in; (void)out_size;
    const float* adjf = (const float*)d_in[0];
    const float* adjs = (const float*)d_in[1];
    const float* adjm = (const float*)d_in[2];
    const float* data = (const float*)d_in[3];
    const float* alf  = (const float*)d_in[4];
    const float* als  = (const float*)d_in[5];
    const float* gw   = (const float*)d_in[6];
    const float* gb   = (const float*)d_in[7];
    const float* gg   = (const float*)d_in[8];
    const float* gbe  = (const float*)d_in[9];
    float* out = (float*)d_out;

    cudaFuncSetAttribute(k_gemm, cudaFuncAttributeMaxDynamicSharedMemorySize, DSMEM_GEMM);

    k_prepB<<<512, 256>>>(data);
    k_blend<<<1024, 256>>>(adjf, adjs, adjm, alf, als);

    for (int h = 0; h < 3; ++h) {
        if (h < 2) {
            k_gemm<<<dim3(128, 2), 256, DSMEM_GEMM>>>(0);
            k_combine<<<128, 256>>>(0, 0);
        } else {
            // last hop: only rows 4096..8191 are consumed (GLU segment)
            k_gemm<<<dim3(64, 2), 256, DSMEM_GEMM>>>(4096);
            k_combine<<<64, 256>>>(4096, 1);
        }
        k_glu<<<dim3(32, 4), 128>>>(gw + h * 2048, gb + h * 128,
                                    gg + h * 128, gbe + h * 128, out, h == 0 ? 1 : 0);
    }
}

// round 14
// speedup vs baseline: 1.3124x; 1.1094x over previous
#include <cuda_runtime.h>
#include <cuda_bf16.h>
#include <math.h>
#include <stdint.h>

#define VN    8192
#define NCOL  64
#define KA    72            // smem row stride in bf16 (144B, LDSM conflict-free)

// smem plane byte offsets within one buffer (M-tile 64, k-tile 64)
#define AHI_OFF 0
#define ALO_OFF 9216        // 64*72*2
#define BHI_OFF 18432
#define BLO_OFF 27648
#define BUFSZ   36864
#define STAGES  3
#define DSMEM_GEMM (STAGES*BUFSZ)   // 110592

// ---------------- device scratch ---------------------------------------------
__device__ __nv_bfloat16 g_adjh[(size_t)VN * VN];   // blended adj, bf16 hi
__device__ __nv_bfloat16 g_adjl[(size_t)VN * VN];   // bf16 lo residual
__device__ float g_rowsum[VN];
__device__ float g_part[2][(size_t)VN * NCOL];
__device__ float g_X[(size_t)VN * NCOL];            // hop output [v][col]
__device__ __nv_bfloat16 g_XTh[(size_t)NCOL * VN];  // B operand, split, [col][w]
__device__ __nv_bfloat16 g_XTl[(size_t)NCOL * VN];
__device__ float g_M[64 * 256];                     // x xT partials [sblk][16*16]
__device__ float g_S[64 * 16];                      // x partials   [sblk][16]

// ---------------- helpers ------------------------------------------------------
__device__ __forceinline__ uint32_t smem_u32(const void* p) {
    uint32_t a;
    asm("{ .reg .u64 t; cvta.to.shared.u64 t, %1; cvt.u32.u64 %0, t; }" : "=r"(a) : "l"(p));
    return a;
}
__device__ __forceinline__ void bsplit(float x, float y, uint32_t& hi, uint32_t& lo) {
    __nv_bfloat162 h = __floats2bfloat162_rn(x, y);
    float hx = __bfloat162float(h.x), hy = __bfloat162float(h.y);
    __nv_bfloat162 l = __floats2bfloat162_rn(x - hx, y - hy);
    hi = *reinterpret_cast<uint32_t*>(&h);
    lo = *reinterpret_cast<uint32_t*>(&l);
}
__device__ __forceinline__ void mma_bf16(float* c,
    uint32_t a0, uint32_t a1, uint32_t a2, uint32_t a3, uint32_t b0, uint32_t b1) {
    asm volatile(
        "mma.sync.aligned.m16n8k16.row.col.f32.bf16.bf16.f32 "
        "{%0,%1,%2,%3}, {%4,%5,%6,%7}, {%8,%9}, {%0,%1,%2,%3};"
        : "+f"(c[0]), "+f"(c[1]), "+f"(c[2]), "+f"(c[3])
        : "r"(a0), "r"(a1), "r"(a2), "r"(a3), "r"(b0), "r"(b1));
}
__device__ __forceinline__ void ldsm4(uint32_t addr, uint32_t* r) {
    asm volatile("ldmatrix.sync.aligned.m8n8.x4.shared.b16 {%0,%1,%2,%3}, [%4];"
        : "=r"(r[0]), "=r"(r[1]), "=r"(r[2]), "=r"(r[3]) : "r"(addr));
}
__device__ __forceinline__ void cpa16(uint32_t dst, const void* src) {
    asm volatile("cp.async.cg.shared.global [%0], [%1], 16;" :: "r"(dst), "l"(src) : "memory");
}
#define CP_COMMIT() asm volatile("cp.async.commit_group;" ::: "memory")

// one 64x64x64 k-tile; warp = 16 rows x 32 cols, 3-term bf16 split (chained acc)
__device__ __forceinline__ void mma_tile(uint32_t base, float acc[4][4],
                                         uint32_t aoff, const uint32_t* boff) {
#pragma unroll
    for (int ks = 0; ks < 4; ++ks) {
        const uint32_t kb = ks * 32;
        uint32_t ah[4], al[4];
        ldsm4(base + AHI_OFF + aoff + kb, ah);
        ldsm4(base + ALO_OFF + aoff + kb, al);
#pragma unroll
        for (int g = 0; g < 2; ++g) {
            uint32_t bh[4], bl[4];
            ldsm4(base + BHI_OFF + boff[g] + kb, bh);
            ldsm4(base + BLO_OFF + boff[g] + kb, bl);
            mma_bf16(acc[2*g],   ah[0],ah[1],ah[2],ah[3], bh[0],bh[1]);
            mma_bf16(acc[2*g],   ah[0],ah[1],ah[2],ah[3], bl[0],bl[1]);
            mma_bf16(acc[2*g],   al[0],al[1],al[2],al[3], bh[0],bh[1]);
            mma_bf16(acc[2*g+1], ah[0],ah[1],ah[2],ah[3], bh[2],bh[3]);
            mma_bf16(acc[2*g+1], ah[0],ah[1],ah[2],ah[3], bl[2],bl[3]);
            mma_bf16(acc[2*g+1], al[0],al[1],al[2],al[3], bh[2],bh[3]);
        }
    }
}

// warp layout: rw = wid>>1 (M group of 16), cw = wid&1 (N group of 32)
__device__ __forceinline__ void frag_offsets(int lane, int wid, uint32_t& aoff, uint32_t* boff) {
    const int rr = lane & 7, sel = lane >> 3;
    const int rw = wid >> 1, cw = wid & 1;
    aoff = ((rw * 16 + (sel & 1) * 8 + rr) * KA + (sel >> 1) * 8) * 2;
#pragma unroll
    for (int g = 0; g < 2; ++g)
        boff[g] = ((cw * 32 + g * 16 + (sel >> 1) * 8 + rr) * KA + (sel & 1) * 8) * 2;
}

__device__ __forceinline__ void write_partials(float acc[4][4], int s, int vbase,
                                               int wid, int lane) {
    const int rw = wid >> 1, cw = wid & 1;
    float* dst = g_part[s] + (size_t)(vbase + rw * 16) * NCOL + cw * 32;
    const int gr = lane >> 2, cq = (lane & 3) * 2;
#pragma unroll
    for (int nb = 0; nb < 4; ++nb) {
        const int col = nb * 8 + cq;
        *(float2*)(dst + (size_t)gr * NCOL + col)       = make_float2(acc[nb][0], acc[nb][1]);
        *(float2*)(dst + (size_t)(gr + 8) * NCOL + col) = make_float2(acc[nb][2], acc[nb][3]);
    }
}

// ---------------- fused prep + blend -------------------------------------------
// blocks [0,1024): blend 8 rows each; blocks [1024,1536): prepB (data -> split XT)
__global__ __launch_bounds__(256) void k_prep_blend(
    const float* __restrict__ adjf, const float* __restrict__ adjs,
    const float* __restrict__ adjm,
    const float* __restrict__ alf, const float* __restrict__ als,
    const float* __restrict__ data)
{
    if (blockIdx.x >= 1024) {
        const int fidx = (blockIdx.x - 1024) * 256 + threadIdx.x;   // 131072 float4s
        const int col = fidx >> 11;
        const int w4  = (fidx & 2047) << 2;
        float4 v = *(const float4*)(data + (size_t)col * 16384 + w4);
        uint32_t h0, l0, h1, l1;
        bsplit(v.x, v.y, h0, l0);
        bsplit(v.z, v.w, h1, l1);
        *reinterpret_cast<uint2*>(g_XTh + (size_t)col * VN + w4) = make_uint2(h0, h1);
        *reinterpret_cast<uint2*>(g_XTl + (size_t)col * VN + w4) = make_uint2(l0, l1);
        return;
    }
    const float e0 = expf(alf[0]), e1 = expf(alf[1]);
    const float f0 = expf(als[0]), f1 = expf(als[1]);
    const float w0 = e0 / (e0 + e1), w1 = e1 / (e0 + e1);
    const float w2 = f0 / (f0 + f1), w3 = f1 / (f0 + f1);

    const int wid = threadIdx.x >> 5, lane = threadIdx.x & 31;
    const int row = blockIdx.x * 8 + wid;
    const size_t base = (size_t)row * VN;
    const float* __restrict__ a0 = adjf + base;
    const float* __restrict__ a1 = adjf + (size_t)VN * VN + base;
    const float* __restrict__ b0 = adjs + base;
    const float* __restrict__ b1 = adjs + (size_t)VN * VN + base;
    const float* __restrict__ m0 = adjm + base;
    __nv_bfloat16* __restrict__ dh = g_adjh + base;
    __nv_bfloat16* __restrict__ dl = g_adjl + base;
    float rs = 0.f;
    for (int i = lane; i < 2048; i += 64) {
#pragma unroll
        for (int u = 0; u < 2; ++u) {
            const int o4 = (i + u * 32) * 4;
            float4 a = *(const float4*)(a0 + o4);
            float4 b = *(const float4*)(a1 + o4);
            float4 c = *(const float4*)(b0 + o4);
            float4 d = *(const float4*)(b1 + o4);
            float4 m = *(const float4*)(m0 + o4);
            float4 r;
            r.x = fmaf(w0, a.x, fmaf(w1, b.x, fmaf(w2, c.x, fmaf(w3, d.x, m.x))));
            r.y = fmaf(w0, a.y, fmaf(w1, b.y, fmaf(w2, c.y, fmaf(w3, d.y, m.y))));
            r.z = fmaf(w0, a.z, fmaf(w1, b.z, fmaf(w2, c.z, fmaf(w3, d.z, m.z))));
            r.w = fmaf(w0, a.w, fmaf(w1, b.w, fmaf(w2, c.w, fmaf(w3, d.w, m.w))));
            rs += (r.x + r.y) + (r.z + r.w);
            uint32_t h0, l0, h1, l1;
            bsplit(r.x, r.y, h0, l0);
            bsplit(r.z, r.w, h1, l1);
            *reinterpret_cast<uint2*>(dh + o4) = make_uint2(h0, h1);
            *reinterpret_cast<uint2*>(dl + o4) = make_uint2(l0, l1);
        }
    }
    rs += __shfl_xor_sync(0xffffffffu, rs, 16);
    rs += __shfl_xor_sync(0xffffffffu, rs, 8);
    rs += __shfl_xor_sync(0xffffffffu, rs, 4);
    rs += __shfl_xor_sync(0xffffffffu, rs, 2);
    rs += __shfl_xor_sync(0xffffffffu, rs, 1);
    if (lane == 0) g_rowsum[row] = rs;
}

// ---------------- GLU body (runs inside merged kernel) -------------------------
// 256 threads enter; 128 do work. gb in [0,128): n-tile = gb&31, batch = gb>>5.
__device__ void glu_body(char* smem, int gb, int tid,
    const float* __restrict__ W, const float* __restrict__ bias,
    const float* __restrict__ gamma, const float* __restrict__ beta,
    float* __restrict__ out, int first)
{
    float* Wsm  = (float*)smem;          // 2048
    float* bsm  = Wsm + 2048;            // 128
    float* gsm  = bsm + 128;
    float* besm = gsm + 128;
    float* musm = besm + 128;
    float* rsm  = musm + 128;
    float* Msm  = rsm + 128;             // 256
    float* Ssm  = Msm + 256;             // 16
    if (tid < 128) {
#pragma unroll
        for (int j = 0; j < 16; ++j) Wsm[tid * 16 + j] = W[tid * 16 + j];
        bsm[tid] = bias[tid]; gsm[tid] = gamma[tid]; besm[tid] = beta[tid];
        float m0 = 0.f, m1 = 0.f;
        for (int k = 0; k < 64; ++k) {
            m0 += g_M[k * 256 + tid];
            m1 += g_M[k * 256 + 128 + tid];
        }
        Msm[tid] = m0; Msm[128 + tid] = m1;
        if (tid < 16) {
            float s = 0.f;
            for (int k = 0; k < 64; ++k) s += g_S[k * 16 + tid];
            Ssm[tid] = s;
        }
    }
    __syncthreads();
    if (tid < 128) {
        const float* w = &Wsm[tid * 16];
        const float bb = bsm[tid];
        float q = 0.f, sw = 0.f;
#pragma unroll
        for (int i = 0; i < 16; ++i) {
            const float wi = w[i];
            sw = fmaf(wi, Ssm[i], sw);
            float row = 0.f;
#pragma unroll
            for (int j = 0; j < 16; ++j) row = fmaf(w[j], Msm[i * 16 + j], row);
            q = fmaf(wi, row, q);
        }
        const float N = 16384.f, invN = 1.f / 16384.f;
        const float mu = (sw + N * bb) * invN;
        const float ey2 = (q + 2.f * bb * sw + N * bb * bb) * invN;
        musm[tid] = mu;
        rsm[tid] = rsqrtf(ey2 - mu * mu + 1e-5f);
    }
    __syncthreads();
    if (tid >= 128) return;

    const int n = (gb & 31) * 128 + tid;
    const int b = gb >> 5;
    float xr[16];
    const float* __restrict__ xp = g_X + (size_t)4096 * NCOL + (size_t)n * 64 + b * 16;
#pragma unroll
    for (int j = 0; j < 4; ++j) {
        float4 t = *(const float4*)(xp + j * 4);
        xr[j * 4] = t.x; xr[j * 4 + 1] = t.y; xr[j * 4 + 2] = t.z; xr[j * 4 + 3] = t.w;
    }
    float* op = out + (size_t)b * (64 * 4096) + n;
    for (int f = 0; f < 64; ++f) {
        const float* wl = &Wsm[f * 16];
        const float* wr = &Wsm[(f + 64) * 16];
        float yl = bsm[f], yr = bsm[f + 64];
#pragma unroll
        for (int c = 0; c < 16; ++c) {
            yl = fmaf(wl[c], xr[c], yl);
            yr = fmaf(wr[c], xr[c], yr);
        }
        yl = fmaf(gsm[f] * (yl - musm[f]), rsm[f], besm[f]);
        yr = fmaf(gsm[f + 64] * (yr - musm[f + 64]), rsm[f + 64], besm[f + 64]);
        float val = yl / (1.f + expf(-yr));
        float* po = op + (size_t)f * 4096;
        if (first) *po = val;
        else       *po = fmaxf(*po, val);
    }
}

// ---------------- merged hop GEMM + (previous hop's) GLU ----------------------
// blocks [0, nGemm): GEMM (mt = bid % Mtiles, split = bid / Mtiles)
// blocks [nGemm, nGemm+128): GLU for the PREVIOUS hop (overlaps with GEMM).
__global__ __launch_bounds__(256, 2) void k_gemm_glu(int vstart, int nGemm,
    const float* __restrict__ W, const float* __restrict__ bias,
    const float* __restrict__ gamma, const float* __restrict__ beta,
    float* __restrict__ out, int first)
{
    extern __shared__ __align__(16) char smem[];
    const int tid = threadIdx.x;
    if ((int)blockIdx.x >= nGemm) {
        glu_body(smem, blockIdx.x - nGemm, tid, W, bias, gamma, beta, out, first);
        return;
    }
    const uint32_t base = smem_u32(smem);
    const int lane = tid & 31, wid = tid >> 5;
    const int mtiles = nGemm >> 1;
    const int mt = blockIdx.x % mtiles;
    const int s  = blockIdx.x / mtiles;
    const int vbase = vstart + mt * 64;
    const int kbase = s * 4096;

    uint32_t aoff, boff[2];
    frag_offsets(lane, wid, aoff, boff);

    float acc[4][4];
#pragma unroll
    for (int i = 0; i < 4; ++i)
#pragma unroll
        for (int j = 0; j < 4; ++j) acc[i][j] = 0.f;

    auto issue = [&](int t) {
        const uint32_t dst = base + (uint32_t)(t % STAGES) * BUFSZ;
        const int kg = kbase + t * 64;
#pragma unroll
        for (int j = 0; j < 2; ++j) {
            const int id = tid + 256 * j;
            const int row = id >> 3, ch = id & 7;
            const size_t go = (size_t)(vbase + row) * VN + kg + ch * 8;
            const uint32_t so = (uint32_t)(row * KA + ch * 8) * 2;
            cpa16(dst + AHI_OFF + so, g_adjh + go);
            cpa16(dst + ALO_OFF + so, g_adjl + go);
        }
#pragma unroll
        for (int j = 0; j < 2; ++j) {
            const int id = tid + 256 * j;
            const int n = id >> 3, ch = id & 7;
            const size_t go = (size_t)n * VN + kg + ch * 8;
            const uint32_t so = (uint32_t)(n * KA + ch * 8) * 2;
            cpa16(dst + BHI_OFF + so, g_XTh + go);
            cpa16(dst + BLO_OFF + so, g_XTl + go);
        }
        CP_COMMIT();
    };

    issue(0); issue(1);
    for (int t = 0; t < 64; ++t) {
        if (t < 63) asm volatile("cp.async.wait_group 1;" ::: "memory");
        else        asm volatile("cp.async.wait_group 0;" ::: "memory");
        __syncthreads();
        mma_tile(base + (uint32_t)(t % STAGES) * BUFSZ, acc, aoff, boff);
        if (t + 2 < 64) issue(t + 2);
    }

    write_partials(acc, s, vbase, wid, lane);
}

// ---------------- combine + second-moment BN partials --------------------------
__global__ __launch_bounds__(256) void k_combine(int vstart, int lastHop) {
    __shared__ float sm[64][65];
    __shared__ float rs[64];
    const int tid = threadIdx.x;
    const int vbase = vstart + blockIdx.x * 64;
    if (tid < 64) rs[tid] = g_rowsum[vbase + tid];
    __syncthreads();
#pragma unroll
    for (int j = 0; j < 4; ++j) {
        const int f = tid + j * 256;
        const int r = f >> 4, c = (f & 15) << 2;
        const size_t o = (size_t)(vbase + r) * NCOL + c;
        float4 p = *(const float4*)(g_part[0] + o);
        float4 q = *(const float4*)(g_part[1] + o);
        const float inv = 1.f / rs[r];
        float4 v;
        v.x = (p.x + q.x) * inv; v.y = (p.y + q.y) * inv;
        v.z = (p.z + q.z) * inv; v.w = (p.w + q.w) * inv;
        *(float4*)(g_X + o) = v;
        sm[r][c] = v.x; sm[r][c + 1] = v.y; sm[r][c + 2] = v.z; sm[r][c + 3] = v.w;
    }
    __syncthreads();
    if (!lastHop) {
        const int col = tid >> 2;
        const int v0 = (tid & 3) << 4;
#pragma unroll
        for (int j = 0; j < 4; ++j) {
            const int v = v0 + j * 4;
            float4 x;
            x.x = sm[v][col]; x.y = sm[v + 1][col]; x.z = sm[v + 2][col]; x.w = sm[v + 3][col];
            uint32_t h0, l0, h1, l1;
            bsplit(x.x, x.y, h0, l0);
            bsplit(x.z, x.w, h1, l1);
            *reinterpret_cast<uint2*>(g_XTh + (size_t)col * VN + vbase + v) = make_uint2(h0, h1);
            *reinterpret_cast<uint2*>(g_XTl + (size_t)col * VN + vbase + v) = make_uint2(l0, l1);
        }
    }
    if (vbase >= 4096) {
        const int i = tid >> 4, jj = tid & 15;
        float mij = 0.f, si = 0.f;
        for (int r = 0; r < 64; ++r) {
#pragma unroll
            for (int b = 0; b < 4; ++b) {
                const float xi = sm[r][b * 16 + i];
                const float xj = sm[r][b * 16 + jj];
                mij = fmaf(xi, xj, mij);
                if (jj == 0) si += xi;
            }
        }
        const int sblk = (vbase - 4096) >> 6;
        g_M[sblk * 256 + tid] = mij;
        if (jj == 0) g_S[sblk * 16 + i] = si;
    }
}

// ---------------- launch -----------------------------------------------------
extern "C" void kernel_launch(void* const* d_in, const int* in_sizes, int n_in,
                              void* d_out, int out_size)
{
    (void)in_sizes; (void)n_in; (void)out_size;
    const float* adjf = (const float*)d_in[0];
    const float* adjs = (const float*)d_in[1];
    const float* adjm = (const float*)d_in[2];
    const float* data = (const float*)d_in[3];
    const float* alf  = (const float*)d_in[4];
    const float* als  = (const float*)d_in[5];
    const float* gw   = (const float*)d_in[6];
    const float* gb   = (const float*)d_in[7];
    const float* gg   = (const float*)d_in[8];
    const float* gbe  = (const float*)d_in[9];
    float* out = (float*)d_out;

    cudaFuncSetAttribute(k_gemm_glu, cudaFuncAttributeMaxDynamicSharedMemorySize, DSMEM_GEMM);

    // fused prep + blend
    k_prep_blend<<<1536, 256>>>(adjf, adjs, adjm, alf, als, data);

    // hop 1 GEMM (no glu yet)
    k_gemm_glu<<<256, 256, DSMEM_GEMM>>>(0, 256, gw, gb, gg, gbe, out, 1);
    k_combine<<<128, 256>>>(0, 0);

    // hop 2 GEMM + hop-1 GLU (first=1)
    k_gemm_glu<<<384, 256, DSMEM_GEMM>>>(0, 256, gw, gb, gg, gbe, out, 1);
    k_combine<<<128, 256>>>(0, 0);

    // hop 3 GEMM (rows 4096..8191 only) + hop-2 GLU
    k_gemm_glu<<<256, 256, DSMEM_GEMM>>>(4096, 128,
        gw + 2048, gb + 128, gg + 128, gbe + 128, out, 0);
    k_combine<<<64, 256>>>(4096, 1);

    // hop-3 GLU standalone
    k_gemm_glu<<<128, 256, DSMEM_GEMM>>>(0, 0,
        gw + 4096, gb + 256, gg + 256, gbe + 256, out, 0);
}

// round 15
// speedup vs baseline: 1.3226x; 1.0078x over previous
#include <cuda_runtime.h>
#include <cuda_bf16.h>
#include <math.h>
#include <stdint.h>

#define VN    8192
#define NCOL  64
#define KA    72            // smem row stride in bf16 (144B, LDSM conflict-free)

// smem plane byte offsets within one buffer (M-tile 64, k-tile 64)
#define AHI_OFF 0
#define ALO_OFF 9216        // 64*72*2
#define BHI_OFF 18432
#define BLO_OFF 27648
#define BUFSZ   36864
#define STAGES  3
#define DSMEM_GEMM (STAGES*BUFSZ)   // 110592

// ---------------- device scratch ---------------------------------------------
__device__ __nv_bfloat16 g_adjh[(size_t)VN * VN];   // blended adj, bf16 hi
__device__ __nv_bfloat16 g_adjl[(size_t)VN * VN];   // bf16 lo residual
__device__ float g_rowsum[VN];
__device__ float g_part[2][(size_t)VN * NCOL];
__device__ float g_X2[2][(size_t)VN * NCOL];        // hop output, hop-parity buffered
__device__ __nv_bfloat16 g_XTh2[2][(size_t)NCOL * VN];
__device__ __nv_bfloat16 g_XTl2[2][(size_t)NCOL * VN];
__device__ float g_M2[2][64 * 256];                 // x xT partials, parity buffered
__device__ float g_S2[2][64 * 16];
__device__ unsigned g_sem[3 * 128];                 // split-K arrival counters (self-resetting)

// ---------------- helpers ------------------------------------------------------
__device__ __forceinline__ uint32_t smem_u32(const void* p) {
    uint32_t a;
    asm("{ .reg .u64 t; cvta.to.shared.u64 t, %1; cvt.u32.u64 %0, t; }" : "=r"(a) : "l"(p));
    return a;
}
__device__ __forceinline__ void bsplit(float x, float y, uint32_t& hi, uint32_t& lo) {
    __nv_bfloat162 h = __floats2bfloat162_rn(x, y);
    float hx = __bfloat162float(h.x), hy = __bfloat162float(h.y);
    __nv_bfloat162 l = __floats2bfloat162_rn(x - hx, y - hy);
    hi = *reinterpret_cast<uint32_t*>(&h);
    lo = *reinterpret_cast<uint32_t*>(&l);
}
__device__ __forceinline__ void mma_bf16(float* c,
    uint32_t a0, uint32_t a1, uint32_t a2, uint32_t a3, uint32_t b0, uint32_t b1) {
    asm volatile(
        "mma.sync.aligned.m16n8k16.row.col.f32.bf16.bf16.f32 "
        "{%0,%1,%2,%3}, {%4,%5,%6,%7}, {%8,%9}, {%0,%1,%2,%3};"
        : "+f"(c[0]), "+f"(c[1]), "+f"(c[2]), "+f"(c[3])
        : "r"(a0), "r"(a1), "r"(a2), "r"(a3), "r"(b0), "r"(b1));
}
__device__ __forceinline__ void ldsm4(uint32_t addr, uint32_t* r) {
    asm volatile("ldmatrix.sync.aligned.m8n8.x4.shared.b16 {%0,%1,%2,%3}, [%4];"
        : "=r"(r[0]), "=r"(r[1]), "=r"(r[2]), "=r"(r[3]) : "r"(addr));
}
__device__ __forceinline__ void cpa16(uint32_t dst, const void* src) {
    asm volatile("cp.async.cg.shared.global [%0], [%1], 16;" :: "r"(dst), "l"(src) : "memory");
}
#define CP_COMMIT() asm volatile("cp.async.commit_group;" ::: "memory")

// one 64x64x64 k-tile; warp = 16 rows x 32 cols, 3-term bf16 split (chained acc)
__device__ __forceinline__ void mma_tile(uint32_t base, float acc[4][4],
                                         uint32_t aoff, const uint32_t* boff) {
#pragma unroll
    for (int ks = 0; ks < 4; ++ks) {
        const uint32_t kb = ks * 32;
        uint32_t ah[4], al[4];
        ldsm4(base + AHI_OFF + aoff + kb, ah);
        ldsm4(base + ALO_OFF + aoff + kb, al);
#pragma unroll
        for (int g = 0; g < 2; ++g) {
            uint32_t bh[4], bl[4];
            ldsm4(base + BHI_OFF + boff[g] + kb, bh);
            ldsm4(base + BLO_OFF + boff[g] + kb, bl);
            mma_bf16(acc[2*g],   ah[0],ah[1],ah[2],ah[3], bh[0],bh[1]);
            mma_bf16(acc[2*g],   ah[0],ah[1],ah[2],ah[3], bl[0],bl[1]);
            mma_bf16(acc[2*g],   al[0],al[1],al[2],al[3], bh[0],bh[1]);
            mma_bf16(acc[2*g+1], ah[0],ah[1],ah[2],ah[3], bh[2],bh[3]);
            mma_bf16(acc[2*g+1], ah[0],ah[1],ah[2],ah[3], bl[2],bl[3]);
            mma_bf16(acc[2*g+1], al[0],al[1],al[2],al[3], bh[2],bh[3]);
        }
    }
}

// warp layout: rw = wid>>1 (M group of 16), cw = wid&1 (N group of 32)
__device__ __forceinline__ void frag_offsets(int lane, int wid, uint32_t& aoff, uint32_t* boff) {
    const int rr = lane & 7, sel = lane >> 3;
    const int rw = wid >> 1, cw = wid & 1;
    aoff = ((rw * 16 + (sel & 1) * 8 + rr) * KA + (sel >> 1) * 8) * 2;
#pragma unroll
    for (int g = 0; g < 2; ++g)
        boff[g] = ((cw * 32 + g * 16 + (sel >> 1) * 8 + rr) * KA + (sel & 1) * 8) * 2;
}

__device__ __forceinline__ void write_partials(float acc[4][4], int s, int vbase,
                                               int wid, int lane) {
    const int rw = wid >> 1, cw = wid & 1;
    float* dst = g_part[s] + (size_t)(vbase + rw * 16) * NCOL + cw * 32;
    const int gr = lane >> 2, cq = (lane & 3) * 2;
#pragma unroll
    for (int nb = 0; nb < 4; ++nb) {
        const int col = nb * 8 + cq;
        *(float2*)(dst + (size_t)gr * NCOL + col)       = make_float2(acc[nb][0], acc[nb][1]);
        *(float2*)(dst + (size_t)(gr + 8) * NCOL + col) = make_float2(acc[nb][2], acc[nb][3]);
    }
}

// ---------------- fused prep + blend -------------------------------------------
__global__ __launch_bounds__(256) void k_prep_blend(
    const float* __restrict__ adjf, const float* __restrict__ adjs,
    const float* __restrict__ adjm,
    const float* __restrict__ alf, const float* __restrict__ als,
    const float* __restrict__ data)
{
    if (blockIdx.x >= 1024) {
        const int fidx = (blockIdx.x - 1024) * 256 + threadIdx.x;   // 131072 float4s
        const int col = fidx >> 11;
        const int w4  = (fidx & 2047) << 2;
        float4 v = *(const float4*)(data + (size_t)col * 16384 + w4);
        uint32_t h0, l0, h1, l1;
        bsplit(v.x, v.y, h0, l0);
        bsplit(v.z, v.w, h1, l1);
        *reinterpret_cast<uint2*>(g_XTh2[0] + (size_t)col * VN + w4) = make_uint2(h0, h1);
        *reinterpret_cast<uint2*>(g_XTl2[0] + (size_t)col * VN + w4) = make_uint2(l0, l1);
        return;
    }
    const float e0 = expf(alf[0]), e1 = expf(alf[1]);
    const float f0 = expf(als[0]), f1 = expf(als[1]);
    const float w0 = e0 / (e0 + e1), w1 = e1 / (e0 + e1);
    const float w2 = f0 / (f0 + f1), w3 = f1 / (f0 + f1);

    const int wid = threadIdx.x >> 5, lane = threadIdx.x & 31;
    const int row = blockIdx.x * 8 + wid;
    const size_t base = (size_t)row * VN;
    const float* __restrict__ a0 = adjf + base;
    const float* __restrict__ a1 = adjf + (size_t)VN * VN + base;
    const float* __restrict__ b0 = adjs + base;
    const float* __restrict__ b1 = adjs + (size_t)VN * VN + base;
    const float* __restrict__ m0 = adjm + base;
    __nv_bfloat16* __restrict__ dh = g_adjh + base;
    __nv_bfloat16* __restrict__ dl = g_adjl + base;
    float rs = 0.f;
    for (int i = lane; i < 2048; i += 64) {
#pragma unroll
        for (int u = 0; u < 2; ++u) {
            const int o4 = (i + u * 32) * 4;
            float4 a = *(const float4*)(a0 + o4);
            float4 b = *(const float4*)(a1 + o4);
            float4 c = *(const float4*)(b0 + o4);
            float4 d = *(const float4*)(b1 + o4);
            float4 m = *(const float4*)(m0 + o4);
            float4 r;
            r.x = fmaf(w0, a.x, fmaf(w1, b.x, fmaf(w2, c.x, fmaf(w3, d.x, m.x))));
            r.y = fmaf(w0, a.y, fmaf(w1, b.y, fmaf(w2, c.y, fmaf(w3, d.y, m.y))));
            r.z = fmaf(w0, a.z, fmaf(w1, b.z, fmaf(w2, c.z, fmaf(w3, d.z, m.z))));
            r.w = fmaf(w0, a.w, fmaf(w1, b.w, fmaf(w2, c.w, fmaf(w3, d.w, m.w))));
            rs += (r.x + r.y) + (r.z + r.w);
            uint32_t h0, l0, h1, l1;
            bsplit(r.x, r.y, h0, l0);
            bsplit(r.z, r.w, h1, l1);
            *reinterpret_cast<uint2*>(dh + o4) = make_uint2(h0, h1);
            *reinterpret_cast<uint2*>(dl + o4) = make_uint2(l0, l1);
        }
    }
    rs += __shfl_xor_sync(0xffffffffu, rs, 16);
    rs += __shfl_xor_sync(0xffffffffu, rs, 8);
    rs += __shfl_xor_sync(0xffffffffu, rs, 4);
    rs += __shfl_xor_sync(0xffffffffu, rs, 2);
    rs += __shfl_xor_sync(0xffffffffu, rs, 1);
    if (lane == 0) g_rowsum[row] = rs;
}

// ---------------- combine body (runs in split-K finisher CTA) ------------------
// reduces both split-K partials, normalizes -> g_X2[hop&1], writes transposed
// split B into g_XT*[(hop+1)&1] (unless lastHop), M/S partials into parity hop&1.
__device__ void combine_body(char* raw, int vbase, int tid, int lastHop, int hop) {
    float (*sm)[65] = (float(*)[65])raw;
    float* rs = (float*)(raw + 64 * 65 * sizeof(float));
    const int xp = hop & 1;
    if (tid < 64) rs[tid] = g_rowsum[vbase + tid];
    __syncthreads();
#pragma unroll
    for (int j = 0; j < 4; ++j) {
        const int f = tid + j * 256;
        const int r = f >> 4, c = (f & 15) << 2;
        const size_t o = (size_t)(vbase + r) * NCOL + c;
        float4 p = *(const float4*)(g_part[0] + o);
        float4 q = *(const float4*)(g_part[1] + o);
        const float inv = 1.f / rs[r];
        float4 v;
        v.x = (p.x + q.x) * inv; v.y = (p.y + q.y) * inv;
        v.z = (p.z + q.z) * inv; v.w = (p.w + q.w) * inv;
        *(float4*)(g_X2[xp] + o) = v;
        sm[r][c] = v.x; sm[r][c + 1] = v.y; sm[r][c + 2] = v.z; sm[r][c + 3] = v.w;
    }
    __syncthreads();
    if (!lastHop) {
        const int xo = (hop + 1) & 1;
        const int col = tid >> 2;
        const int v0 = (tid & 3) << 4;
#pragma unroll
        for (int j = 0; j < 4; ++j) {
            const int v = v0 + j * 4;
            float4 x;
            x.x = sm[v][col]; x.y = sm[v + 1][col]; x.z = sm[v + 2][col]; x.w = sm[v + 3][col];
            uint32_t h0, l0, h1, l1;
            bsplit(x.x, x.y, h0, l0);
            bsplit(x.z, x.w, h1, l1);
            *reinterpret_cast<uint2*>(g_XTh2[xo] + (size_t)col * VN + vbase + v) = make_uint2(h0, h1);
            *reinterpret_cast<uint2*>(g_XTl2[xo] + (size_t)col * VN + vbase + v) = make_uint2(l0, l1);
        }
    }
    if (vbase >= 4096) {
        const int i = tid >> 4, jj = tid & 15;
        float mij = 0.f, si = 0.f;
        for (int r = 0; r < 64; ++r) {
#pragma unroll
            for (int b = 0; b < 4; ++b) {
                const float xi = sm[r][b * 16 + i];
                const float xj = sm[r][b * 16 + jj];
                mij = fmaf(xi, xj, mij);
                if (jj == 0) si += xi;
            }
        }
        const int sblk = (vbase - 4096) >> 6;
        g_M2[xp][sblk * 256 + tid] = mij;
        if (jj == 0) g_S2[xp][sblk * 16 + i] = si;
    }
}

// ---------------- GLU body ------------------------------------------------------
__device__ void glu_body(char* smem, int gb, int tid, int gluPar,
    const float* __restrict__ W, const float* __restrict__ bias,
    const float* __restrict__ gamma, const float* __restrict__ beta,
    float* __restrict__ out, int first)
{
    float* Wsm  = (float*)smem;          // 2048
    float* bsm  = Wsm + 2048;            // 128
    float* gsm  = bsm + 128;
    float* besm = gsm + 128;
    float* musm = besm + 128;
    float* rsm  = musm + 128;
    float* Msm  = rsm + 128;             // 256
    float* Ssm  = Msm + 256;             // 16
    const float* __restrict__ gM = g_M2[gluPar];
    const float* __restrict__ gS = g_S2[gluPar];
    if (tid < 128) {
#pragma unroll
        for (int j = 0; j < 16; ++j) Wsm[tid * 16 + j] = W[tid * 16 + j];
        bsm[tid] = bias[tid]; gsm[tid] = gamma[tid]; besm[tid] = beta[tid];
        float m0 = 0.f, m1 = 0.f;
        for (int k = 0; k < 64; ++k) {
            m0 += gM[k * 256 + tid];
            m1 += gM[k * 256 + 128 + tid];
        }
        Msm[tid] = m0; Msm[128 + tid] = m1;
        if (tid < 16) {
            float s = 0.f;
            for (int k = 0; k < 64; ++k) s += gS[k * 16 + tid];
            Ssm[tid] = s;
        }
    }
    __syncthreads();
    if (tid < 128) {
        const float* w = &Wsm[tid * 16];
        const float bb = bsm[tid];
        float q = 0.f, sw = 0.f;
#pragma unroll
        for (int i = 0; i < 16; ++i) {
            const float wi = w[i];
            sw = fmaf(wi, Ssm[i], sw);
            float row = 0.f;
#pragma unroll
            for (int j = 0; j < 16; ++j) row = fmaf(w[j], Msm[i * 16 + j], row);
            q = fmaf(wi, row, q);
        }
        const float N = 16384.f, invN = 1.f / 16384.f;
        const float mu = (sw + N * bb) * invN;
        const float ey2 = (q + 2.f * bb * sw + N * bb * bb) * invN;
        musm[tid] = mu;
        rsm[tid] = rsqrtf(ey2 - mu * mu + 1e-5f);
    }
    __syncthreads();
    if (tid >= 128) return;

    const int n = (gb & 31) * 128 + tid;
    const int b = gb >> 5;
    float xr[16];
    const float* __restrict__ xp = g_X2[gluPar] + (size_t)4096 * NCOL + (size_t)n * 64 + b * 16;
#pragma unroll
    for (int j = 0; j < 4; ++j) {
        float4 t = *(const float4*)(xp + j * 4);
        xr[j * 4] = t.x; xr[j * 4 + 1] = t.y; xr[j * 4 + 2] = t.z; xr[j * 4 + 3] = t.w;
    }
    float* op = out + (size_t)b * (64 * 4096) + n;
    for (int f = 0; f < 64; ++f) {
        const float* wl = &Wsm[f * 16];
        const float* wr = &Wsm[(f + 64) * 16];
        float yl = bsm[f], yr = bsm[f + 64];
#pragma unroll
        for (int c = 0; c < 16; ++c) {
            yl = fmaf(wl[c], xr[c], yl);
            yr = fmaf(wr[c], xr[c], yr);
        }
        yl = fmaf(gsm[f] * (yl - musm[f]), rsm[f], besm[f]);
        yr = fmaf(gsm[f + 64] * (yr - musm[f + 64]), rsm[f + 64], besm[f + 64]);
        float val = yl / (1.f + expf(-yr));
        float* po = op + (size_t)f * 4096;
        if (first) *po = val;
        else       *po = fmaxf(*po, val);
    }
}

// ---------------- merged hop GEMM + fused combine + previous hop's GLU ---------
// blocks [0, nGemm): GEMM (mt = bid % Mtiles, split = bid / Mtiles); the second
// split-K CTA to finish each M-tile runs the combine in-place.
// blocks [nGemm, ...): GLU for the PREVIOUS hop (overlaps with GEMM).
__global__ __launch_bounds__(256, 2) void k_gemm_glu(int vstart, int nGemm,
    int hop, int lastHop, int gluPar,
    const float* __restrict__ W, const float* __restrict__ bias,
    const float* __restrict__ gamma, const float* __restrict__ beta,
    float* __restrict__ out, int first)
{
    extern __shared__ __align__(16) char smem[];
    const int tid = threadIdx.x;
    if ((int)blockIdx.x >= nGemm) {
        glu_body(smem, blockIdx.x - nGemm, tid, gluPar, W, bias, gamma, beta, out, first);
        return;
    }
    const uint32_t base = smem_u32(smem);
    const int lane = tid & 31, wid = tid >> 5;
    const int mtiles = nGemm >> 1;
    const int mt = blockIdx.x % mtiles;
    const int s  = blockIdx.x / mtiles;
    const int vbase = vstart + mt * 64;
    const int kbase = s * 4096;
    const __nv_bfloat16* __restrict__ XTh = g_XTh2[hop & 1];
    const __nv_bfloat16* __restrict__ XTl = g_XTl2[hop & 1];

    uint32_t aoff, boff[2];
    frag_offsets(lane, wid, aoff, boff);

    float acc[4][4];
#pragma unroll
    for (int i = 0; i < 4; ++i)
#pragma unroll
        for (int j = 0; j < 4; ++j) acc[i][j] = 0.f;

    auto issue = [&](int t) {
        const uint32_t dst = base + (uint32_t)(t % STAGES) * BUFSZ;
        const int kg = kbase + t * 64;
#pragma unroll
        for (int j = 0; j < 2; ++j) {
            const int id = tid + 256 * j;
            const int row = id >> 3, ch = id & 7;
            const size_t go = (size_t)(vbase + row) * VN + kg + ch * 8;
            const uint32_t so = (uint32_t)(row * KA + ch * 8) * 2;
            cpa16(dst + AHI_OFF + so, g_adjh + go);
            cpa16(dst + ALO_OFF + so, g_adjl + go);
        }
#pragma unroll
        for (int j = 0; j < 2; ++j) {
            const int id = tid + 256 * j;
            const int n = id >> 3, ch = id & 7;
            const size_t go = (size_t)n * VN + kg + ch * 8;
            const uint32_t so = (uint32_t)(n * KA + ch * 8) * 2;
            cpa16(dst + BHI_OFF + so, XTh + go);
            cpa16(dst + BLO_OFF + so, XTl + go);
        }
        CP_COMMIT();
    };

    issue(0); issue(1);
    for (int t = 0; t < 64; ++t) {
        if (t < 63) asm volatile("cp.async.wait_group 1;" ::: "memory");
        else        asm volatile("cp.async.wait_group 0;" ::: "memory");
        __syncthreads();
        mma_tile(base + (uint32_t)(t % STAGES) * BUFSZ, acc, aoff, boff);
        if (t + 2 < 64) issue(t + 2);
    }

    write_partials(acc, s, vbase, wid, lane);

    // split-K arrival; second CTA runs the combine for this M-tile
    __threadfence();
    __syncthreads();
    __shared__ unsigned lastArr;
    const int slot = hop * 128 + (vbase >> 6);
    if (tid == 0) lastArr = atomicAdd(&g_sem[slot], 1u);
    __syncthreads();
    if (lastArr == 1) {
        __threadfence();   // acquire: other CTA's partials now visible
        combine_body(smem, vbase, tid, lastHop, hop);
        __syncthreads();
        if (tid == 0) g_sem[slot] = 0;   // reset for next launch / graph replay
    }
}

// ---------------- launch -----------------------------------------------------
extern "C" void kernel_launch(void* const* d_in, const int* in_sizes, int n_in,
                              void* d_out, int out_size)
{
    (void)in_sizes; (void)n_in; (void)out_size;
    const float* adjf = (const float*)d_in[0];
    const float* adjs = (const float*)d_in[1];
    const float* adjm = (const float*)d_in[2];
    const float* data = (const float*)d_in[3];
    const float* alf  = (const float*)d_in[4];
    const float* als  = (const float*)d_in[5];
    const float* gw   = (const float*)d_in[6];
    const float* gb   = (const float*)d_in[7];
    const float* gg   = (const float*)d_in[8];
    const float* gbe  = (const float*)d_in[9];
    float* out = (float*)d_out;

    cudaFuncSetAttribute(k_gemm_glu, cudaFuncAttributeMaxDynamicSharedMemorySize, DSMEM_GEMM);

    // fused prep + blend
    k_prep_blend<<<1536, 256>>>(adjf, adjs, adjm, alf, als, data);

    // hop 0 GEMM + combine0 (writes X[0], XT[1], M/S[0])
    k_gemm_glu<<<256, 256, DSMEM_GEMM>>>(0, 256, 0, 0, 0,
        gw, gb, gg, gbe, out, 1);

    // hop 1 GEMM (reads XT[1]) + combine1 (writes X[1], XT[0], M/S[1]) + GLU hop0 (reads par 0)
    k_gemm_glu<<<384, 256, DSMEM_GEMM>>>(0, 256, 1, 0, 0,
        gw, gb, gg, gbe, out, 1);

    // hop 2 GEMM rows 4096.. (reads XT[0]) + combine2 (writes X[0], M/S[0]) + GLU hop1 (par 1)
    k_gemm_glu<<<256, 256, DSMEM_GEMM>>>(4096, 128, 2, 1, 1,
        gw + 2048, gb + 128, gg + 128, gbe + 128, out, 0);

    // GLU hop2 standalone (par 0)
    k_gemm_glu<<<128, 256, DSMEM_GEMM>>>(0, 0, 0, 0, 0,
        gw + 4096, gb + 256, gg + 256, gbe + 256, out, 0);
}